// round 4
// baseline (speedup 1.0000x reference)
#include <cuda_runtime.h>
#include <cstdint>

#define D_FEAT   128
#define H_FEAT   128
#define N_NODES  100000
#define N_EDGES  800000

#define TM       64      // rows (edges/nodes) per CTA
#define BK       16      // K-chunk
#define NTHREADS 256
#define XS_STRIDE (BK + 4)      // 20: 4*20=80 ≡ 16 mod 32 -> conflict-free row reads
#define HS_STRIDE (D_FEAT + 4)  // 132: 4*132=528 ≡ 16 mod 32

// scatter-sum scratch (51.2 MB). __device__ global: allowed (no alloc).
__device__ float g_agg[(size_t)N_NODES * D_FEAT];

// ---- packed f32x2 helpers (Blackwell FFMA2 path, PTX-only) ----
__device__ __forceinline__ void fma2(unsigned long long &c,
                                     unsigned long long a,
                                     unsigned long long b) {
    asm("fma.rn.f32x2 %0, %1, %2, %3;" : "=l"(c) : "l"(a), "l"(b), "l"(c));
}
__device__ __forceinline__ unsigned long long pack2(float lo, float hi) {
    unsigned long long r;
    asm("mov.b64 %0, {%1, %2};" : "=l"(r) : "f"(lo), "f"(hi));
    return r;
}
__device__ __forceinline__ void unpack2(unsigned long long v, float &lo, float &hi) {
    asm("mov.b64 {%0, %1}, %2;" : "=f"(lo), "=f"(hi) : "l"(v));
}
__device__ __forceinline__ void red_add4(float* p, float a, float b, float c, float d) {
    asm volatile("red.global.add.v4.f32 [%0], {%1, %2, %3, %4};"
                 :: "l"(p), "f"(a), "f"(b), "f"(c), "f"(d) : "memory");
}

// ============================================================================
// Edge kernel: e_upd = relu([nf[s], nf[r], ef] @ We1 + be1) @ We2 + be2
//   out_edges = ef + e_upd ;  red-add e_upd into g_agg[receiver]
// ============================================================================
__global__ void __launch_bounds__(NTHREADS, 3)
edge_kernel(const float* __restrict__ nf, const float* __restrict__ ef,
            const int* __restrict__ snd, const int* __restrict__ rcv,
            const float* __restrict__ We1, const float* __restrict__ be1,
            const float* __restrict__ We2, const float* __restrict__ be2,
            float* __restrict__ out_edges, float* __restrict__ agg)
{
    __shared__ __align__(16) int   sIdx[TM];
    __shared__ __align__(16) int   rIdx[TM];
    __shared__ __align__(16) float Xs[TM * XS_STRIDE];
    __shared__ __align__(16) float Ws[BK * H_FEAT];
    __shared__ __align__(16) float Hs[TM * HS_STRIDE];

    const int tid = threadIdx.x;
    const int ty = tid >> 4, tx = tid & 15;
    const int r0 = ty * 4, c0 = tx * 8;
    const int e0 = blockIdx.x * TM;

    if (tid < TM) { sIdx[tid] = snd[e0 + tid]; rIdx[tid] = rcv[e0 + tid]; }

    unsigned long long acc[4][4];
    {   // init with layer-1 bias
        ulonglong2 b0 = *(const ulonglong2*)&be1[c0];
        ulonglong2 b1 = *(const ulonglong2*)&be1[c0 + 4];
        #pragma unroll
        for (int i = 0; i < 4; i++) {
            acc[i][0] = b0.x; acc[i][1] = b0.y; acc[i][2] = b1.x; acc[i][3] = b1.y;
        }
    }
    __syncthreads();

    // -------- layer 1: K = 384 over 3 gathered sources, chunks of 16 --------
    for (int chunk = 0; chunk < 24; ++chunk) {
        const int src  = chunk >> 3;          // 0: sender nf, 1: receiver nf, 2: ef
        const int koff = (chunk & 7) * BK;
        {   // load Xs tile: 64 rows x 16 floats = 256 float4 (1/thread)
            const int row = tid >> 2;
            const int j4  = (tid & 3) * 4;
            size_t grow;
            const float* base;
            if (src == 0)      { grow = (size_t)sIdx[row]; base = nf; }
            else if (src == 1) { grow = (size_t)rIdx[row]; base = nf; }
            else               { grow = (size_t)(e0 + row); base = ef; }
            float4 v = *(const float4*)&base[grow * D_FEAT + koff + j4];
            *(float4*)&Xs[row * XS_STRIDE + j4] = v;
        }
        {   // load Ws tile: 16 x 128 = 512 float4 (2/thread)
            const float* wbase = We1 + (size_t)(src * D_FEAT + koff) * H_FEAT;
            #pragma unroll
            for (int t = 0; t < 2; ++t) {
                int q = tid + t * NTHREADS;
                int row = q >> 5, col4 = (q & 31) * 4;
                *(float4*)&Ws[row * H_FEAT + col4] =
                    *(const float4*)&wbase[(size_t)row * H_FEAT + col4];
            }
        }
        __syncthreads();
        #pragma unroll
        for (int kk = 0; kk < BK; ++kk) {
            unsigned long long aa[4];
            #pragma unroll
            for (int i = 0; i < 4; i++) {
                float a = Xs[(r0 + i) * XS_STRIDE + kk];
                aa[i] = pack2(a, a);
            }
            ulonglong2 w0 = *(const ulonglong2*)&Ws[kk * H_FEAT + c0];
            ulonglong2 w1 = *(const ulonglong2*)&Ws[kk * H_FEAT + c0 + 4];
            #pragma unroll
            for (int i = 0; i < 4; i++) {
                fma2(acc[i][0], aa[i], w0.x);
                fma2(acc[i][1], aa[i], w0.y);
                fma2(acc[i][2], aa[i], w1.x);
                fma2(acc[i][3], aa[i], w1.y);
            }
        }
        __syncthreads();
    }

    // -------- ReLU -> Hs --------
    #pragma unroll
    for (int i = 0; i < 4; i++) {
        float h[8];
        unpack2(acc[i][0], h[0], h[1]);
        unpack2(acc[i][1], h[2], h[3]);
        unpack2(acc[i][2], h[4], h[5]);
        unpack2(acc[i][3], h[6], h[7]);
        #pragma unroll
        for (int j = 0; j < 8; j++) h[j] = fmaxf(h[j], 0.0f);
        float* hp = &Hs[(r0 + i) * HS_STRIDE + c0];
        *(float4*)hp       = make_float4(h[0], h[1], h[2], h[3]);
        *(float4*)(hp + 4) = make_float4(h[4], h[5], h[6], h[7]);
    }
    {   // init with layer-2 bias
        ulonglong2 b0 = *(const ulonglong2*)&be2[c0];
        ulonglong2 b1 = *(const ulonglong2*)&be2[c0 + 4];
        #pragma unroll
        for (int i = 0; i < 4; i++) {
            acc[i][0] = b0.x; acc[i][1] = b0.y; acc[i][2] = b1.x; acc[i][3] = b1.y;
        }
    }
    __syncthreads();

    // -------- layer 2: K = 128 from Hs --------
    for (int chunk = 0; chunk < 8; ++chunk) {
        const int koff = chunk * BK;
        #pragma unroll
        for (int t = 0; t < 2; ++t) {
            int q = tid + t * NTHREADS;
            int row = q >> 5, col4 = (q & 31) * 4;
            *(float4*)&Ws[row * H_FEAT + col4] =
                *(const float4*)&We2[(size_t)(koff + row) * H_FEAT + col4];
        }
        __syncthreads();
        #pragma unroll
        for (int kk = 0; kk < BK; ++kk) {
            unsigned long long aa[4];
            #pragma unroll
            for (int i = 0; i < 4; i++) {
                float a = Hs[(r0 + i) * HS_STRIDE + koff + kk];
                aa[i] = pack2(a, a);
            }
            ulonglong2 w0 = *(const ulonglong2*)&Ws[kk * H_FEAT + c0];
            ulonglong2 w1 = *(const ulonglong2*)&Ws[kk * H_FEAT + c0 + 4];
            #pragma unroll
            for (int i = 0; i < 4; i++) {
                fma2(acc[i][0], aa[i], w0.x);
                fma2(acc[i][1], aa[i], w0.y);
                fma2(acc[i][2], aa[i], w1.x);
                fma2(acc[i][3], aa[i], w1.y);
            }
        }
        __syncthreads();
    }

    // -------- epilogue: residual write + scatter-add --------
    #pragma unroll
    for (int i = 0; i < 4; i++) {
        const int e = e0 + r0 + i;
        float u[8];
        unpack2(acc[i][0], u[0], u[1]);
        unpack2(acc[i][1], u[2], u[3]);
        unpack2(acc[i][2], u[4], u[5]);
        unpack2(acc[i][3], u[6], u[7]);

        float* aggp = &agg[(size_t)rIdx[r0 + i] * D_FEAT + c0];
        red_add4(aggp,     u[0], u[1], u[2], u[3]);
        red_add4(aggp + 4, u[4], u[5], u[6], u[7]);

        const float4 efa = *(const float4*)&ef[(size_t)e * D_FEAT + c0];
        const float4 efb = *(const float4*)&ef[(size_t)e * D_FEAT + c0 + 4];
        float4 o0 = make_float4(u[0] + efa.x, u[1] + efa.y, u[2] + efa.z, u[3] + efa.w);
        float4 o1 = make_float4(u[4] + efb.x, u[5] + efb.y, u[6] + efb.z, u[7] + efb.w);
        *(float4*)&out_edges[(size_t)e * D_FEAT + c0]     = o0;
        *(float4*)&out_edges[(size_t)e * D_FEAT + c0 + 4] = o1;
    }
}

// ============================================================================
// Node kernel: n_upd = relu([nf, agg] @ Wn1 + bn1) @ Wn2 + bn2
//   out_nodes = nf + n_upd
// ============================================================================
__global__ void __launch_bounds__(NTHREADS, 3)
node_kernel(const float* __restrict__ nf, const float* __restrict__ agg,
            const float* __restrict__ Wn1, const float* __restrict__ bn1,
            const float* __restrict__ Wn2, const float* __restrict__ bn2,
            float* __restrict__ out_nodes)
{
    __shared__ __align__(16) float Xs[TM * XS_STRIDE];
    __shared__ __align__(16) float Ws[BK * H_FEAT];
    __shared__ __align__(16) float Hs[TM * HS_STRIDE];

    const int tid = threadIdx.x;
    const int ty = tid >> 4, tx = tid & 15;
    const int r0 = ty * 4, c0 = tx * 8;
    const int n0 = blockIdx.x * TM;

    unsigned long long acc[4][4];
    {
        ulonglong2 b0 = *(const ulonglong2*)&bn1[c0];
        ulonglong2 b1 = *(const ulonglong2*)&bn1[c0 + 4];
        #pragma unroll
        for (int i = 0; i < 4; i++) {
            acc[i][0] = b0.x; acc[i][1] = b0.y; acc[i][2] = b1.x; acc[i][3] = b1.y;
        }
    }

    // -------- layer 1: K = 256 over [nf | agg], chunks of 16 --------
    for (int chunk = 0; chunk < 16; ++chunk) {
        const int src  = chunk >> 3;   // 0: nf, 1: agg
        const int koff = (chunk & 7) * BK;
        {
            const int row = tid >> 2;
            const int j4  = (tid & 3) * 4;
            int m = n0 + row;
            if (m >= N_NODES) m = N_NODES - 1;   // clamp (writes are guarded later)
            const float* base = src ? agg : nf;
            float4 v = *(const float4*)&base[(size_t)m * D_FEAT + koff + j4];
            *(float4*)&Xs[row * XS_STRIDE + j4] = v;
        }
        {
            const float* wbase = Wn1 + (size_t)(src * D_FEAT + koff) * H_FEAT;
            #pragma unroll
            for (int t = 0; t < 2; ++t) {
                int q = tid + t * NTHREADS;
                int row = q >> 5, col4 = (q & 31) * 4;
                *(float4*)&Ws[row * H_FEAT + col4] =
                    *(const float4*)&wbase[(size_t)row * H_FEAT + col4];
            }
        }
        __syncthreads();
        #pragma unroll
        for (int kk = 0; kk < BK; ++kk) {
            unsigned long long aa[4];
            #pragma unroll
            for (int i = 0; i < 4; i++) {
                float a = Xs[(r0 + i) * XS_STRIDE + kk];
                aa[i] = pack2(a, a);
            }
            ulonglong2 w0 = *(const ulonglong2*)&Ws[kk * H_FEAT + c0];
            ulonglong2 w1 = *(const ulonglong2*)&Ws[kk * H_FEAT + c0 + 4];
            #pragma unroll
            for (int i = 0; i < 4; i++) {
                fma2(acc[i][0], aa[i], w0.x);
                fma2(acc[i][1], aa[i], w0.y);
                fma2(acc[i][2], aa[i], w1.x);
                fma2(acc[i][3], aa[i], w1.y);
            }
        }
        __syncthreads();
    }

    // -------- ReLU -> Hs --------
    #pragma unroll
    for (int i = 0; i < 4; i++) {
        float h[8];
        unpack2(acc[i][0], h[0], h[1]);
        unpack2(acc[i][1], h[2], h[3]);
        unpack2(acc[i][2], h[4], h[5]);
        unpack2(acc[i][3], h[6], h[7]);
        #pragma unroll
        for (int j = 0; j < 8; j++) h[j] = fmaxf(h[j], 0.0f);
        float* hp = &Hs[(r0 + i) * HS_STRIDE + c0];
        *(float4*)hp       = make_float4(h[0], h[1], h[2], h[3]);
        *(float4*)(hp + 4) = make_float4(h[4], h[5], h[6], h[7]);
    }
    {
        ulonglong2 b0 = *(const ulonglong2*)&bn2[c0];
        ulonglong2 b1 = *(const ulonglong2*)&bn2[c0 + 4];
        #pragma unroll
        for (int i = 0; i < 4; i++) {
            acc[i][0] = b0.x; acc[i][1] = b0.y; acc[i][2] = b1.x; acc[i][3] = b1.y;
        }
    }
    __syncthreads();

    // -------- layer 2: K = 128 from Hs --------
    for (int chunk = 0; chunk < 8; ++chunk) {
        const int koff = chunk * BK;
        #pragma unroll
        for (int t = 0; t < 2; ++t) {
            int q = tid + t * NTHREADS;
            int row = q >> 5, col4 = (q & 31) * 4;
            *(float4*)&Ws[row * H_FEAT + col4] =
                *(const float4*)&Wn2[(size_t)(koff + row) * H_FEAT + col4];
        }
        __syncthreads();
        #pragma unroll
        for (int kk = 0; kk < BK; ++kk) {
            unsigned long long aa[4];
            #pragma unroll
            for (int i = 0; i < 4; i++) {
                float a = Hs[(r0 + i) * HS_STRIDE + koff + kk];
                aa[i] = pack2(a, a);
            }
            ulonglong2 w0 = *(const ulonglong2*)&Ws[kk * H_FEAT + c0];
            ulonglong2 w1 = *(const ulonglong2*)&Ws[kk * H_FEAT + c0 + 4];
            #pragma unroll
            for (int i = 0; i < 4; i++) {
                fma2(acc[i][0], aa[i], w0.x);
                fma2(acc[i][1], aa[i], w0.y);
                fma2(acc[i][2], aa[i], w1.x);
                fma2(acc[i][3], aa[i], w1.y);
            }
        }
        __syncthreads();
    }

    // -------- epilogue: residual write (guarded) --------
    #pragma unroll
    for (int i = 0; i < 4; i++) {
        const int m = n0 + r0 + i;
        if (m < N_NODES) {
            float u[8];
            unpack2(acc[i][0], u[0], u[1]);
            unpack2(acc[i][1], u[2], u[3]);
            unpack2(acc[i][2], u[4], u[5]);
            unpack2(acc[i][3], u[6], u[7]);
            const float4 na = *(const float4*)&nf[(size_t)m * D_FEAT + c0];
            const float4 nb = *(const float4*)&nf[(size_t)m * D_FEAT + c0 + 4];
            float4 o0 = make_float4(u[0] + na.x, u[1] + na.y, u[2] + na.z, u[3] + na.w);
            float4 o1 = make_float4(u[4] + nb.x, u[5] + nb.y, u[6] + nb.z, u[7] + nb.w);
            *(float4*)&out_nodes[(size_t)m * D_FEAT + c0]     = o0;
            *(float4*)&out_nodes[(size_t)m * D_FEAT + c0 + 4] = o1;
        }
    }
}

// ============================================================================
extern "C" void kernel_launch(void* const* d_in, const int* in_sizes, int n_in,
                              void* d_out, int out_size)
{
    const float* nf  = (const float*)d_in[0];
    const float* ef  = (const float*)d_in[1];
    const int*   snd = (const int*)  d_in[2];
    const int*   rcv = (const int*)  d_in[3];
    const float* We1 = (const float*)d_in[4];
    const float* be1 = (const float*)d_in[5];
    const float* We2 = (const float*)d_in[6];
    const float* be2 = (const float*)d_in[7];
    const float* Wn1 = (const float*)d_in[8];
    const float* bn1 = (const float*)d_in[9];
    const float* Wn2 = (const float*)d_in[10];
    const float* bn2 = (const float*)d_in[11];

    float* out_nodes = (float*)d_out;                            // [N, D] first
    float* out_edges = (float*)d_out + (size_t)N_NODES * D_FEAT; // [E, D] second

    float* aggp = nullptr;
    cudaGetSymbolAddress((void**)&aggp, g_agg);
    cudaMemsetAsync(aggp, 0, (size_t)N_NODES * D_FEAT * sizeof(float));

    edge_kernel<<<N_EDGES / TM, NTHREADS>>>(nf, ef, snd, rcv,
                                            We1, be1, We2, be2,
                                            out_edges, aggp);
    node_kernel<<<(N_NODES + TM - 1) / TM, NTHREADS>>>(nf, aggp,
                                                       Wn1, bn1, Wn2, bn2,
                                                       out_nodes);
}

// round 5
// speedup vs baseline: 1.4677x; 1.4677x over previous
#include <cuda_runtime.h>
#include <cstdint>

#define D_FEAT   128
#define H_FEAT   128
#define N_NODES  100000
#define N_EDGES  800000

#define TM       64      // rows (edges/nodes) per CTA
#define BK       16      // K-chunk
#define NTHREADS 128     // 16 (tx) x 8 (ty); thread tile = 8 rows x 8 cols
#define XS_STRIDE (BK + 4)      // 20
#define HS_STRIDE (D_FEAT + 4)  // 132

// scatter-sum scratch (51.2 MB). __device__ global: allowed (no alloc).
__device__ float g_agg[(size_t)N_NODES * D_FEAT];

// ---- packed f32x2 helpers (Blackwell FFMA2 path, PTX-only) ----
__device__ __forceinline__ void fma2(unsigned long long &c,
                                     unsigned long long a,
                                     unsigned long long b) {
    asm("fma.rn.f32x2 %0, %1, %2, %3;" : "=l"(c) : "l"(a), "l"(b), "l"(c));
}
__device__ __forceinline__ unsigned long long pack2(float lo, float hi) {
    unsigned long long r;
    asm("mov.b64 %0, {%1, %2};" : "=l"(r) : "f"(lo), "f"(hi));
    return r;
}
__device__ __forceinline__ void unpack2(unsigned long long v, float &lo, float &hi) {
    asm("mov.b64 {%0, %1}, %2;" : "=f"(lo), "=f"(hi) : "l"(v));
}
__device__ __forceinline__ void red_add4(float* p, float a, float b, float c, float d) {
    asm volatile("red.global.add.v4.f32 [%0], {%1, %2, %3, %4};"
                 :: "l"(p), "f"(a), "f"(b), "f"(c), "f"(d) : "memory");
}

// ============================================================================
// Edge kernel: e_upd = relu([nf[s], nf[r], ef] @ We1 + be1) @ We2 + be2
//   out_edges = ef + e_upd ;  red-add e_upd into g_agg[receiver]
// ============================================================================
__global__ void __launch_bounds__(NTHREADS, 3)
edge_kernel(const float* __restrict__ nf, const float* __restrict__ ef,
            const int* __restrict__ snd, const int* __restrict__ rcv,
            const float* __restrict__ We1, const float* __restrict__ be1,
            const float* __restrict__ We2, const float* __restrict__ be2,
            float* __restrict__ out_edges, float* __restrict__ agg)
{
    __shared__ __align__(16) int   sIdx[TM];
    __shared__ __align__(16) int   rIdx[TM];
    __shared__ __align__(16) float Xs[TM * XS_STRIDE];
    __shared__ __align__(16) float Ws[BK * H_FEAT];
    __shared__ __align__(16) float Hs[TM * HS_STRIDE];

    const int tid = threadIdx.x;
    const int ty = tid >> 4, tx = tid & 15;
    const int r0 = ty * 8, c0 = tx * 8;
    const int e0 = blockIdx.x * TM;

    if (tid < TM) { sIdx[tid] = snd[e0 + tid]; rIdx[tid] = rcv[e0 + tid]; }

    unsigned long long acc[8][4];
    {   // init with layer-1 bias
        ulonglong2 b0 = *(const ulonglong2*)&be1[c0];
        ulonglong2 b1 = *(const ulonglong2*)&be1[c0 + 4];
        #pragma unroll
        for (int i = 0; i < 8; i++) {
            acc[i][0] = b0.x; acc[i][1] = b0.y; acc[i][2] = b1.x; acc[i][3] = b1.y;
        }
    }
    __syncthreads();

    // -------- layer 1: K = 384 over 3 gathered sources, chunks of 16 --------
    for (int chunk = 0; chunk < 24; ++chunk) {
        const int src  = chunk >> 3;          // 0: sender nf, 1: receiver nf, 2: ef
        const int koff = (chunk & 7) * BK;
        {   // Xs tile: 64 rows x 16 floats = 256 float4, 2 per thread
            #pragma unroll
            for (int t = 0; t < 2; ++t) {
                int q = tid + t * NTHREADS;
                int row = q >> 2, j4 = (q & 3) * 4;
                size_t grow;
                const float* base;
                if (src == 0)      { grow = (size_t)sIdx[row]; base = nf; }
                else if (src == 1) { grow = (size_t)rIdx[row]; base = nf; }
                else               { grow = (size_t)(e0 + row); base = ef; }
                float4 v = *(const float4*)&base[grow * D_FEAT + koff + j4];
                *(float4*)&Xs[row * XS_STRIDE + j4] = v;
            }
        }
        {   // Ws tile: 16 x 128 = 512 float4, 4 per thread
            const float* wbase = We1 + (size_t)(src * D_FEAT + koff) * H_FEAT;
            #pragma unroll
            for (int t = 0; t < 4; ++t) {
                int q = tid + t * NTHREADS;
                int row = q >> 5, col4 = (q & 31) * 4;
                *(float4*)&Ws[row * H_FEAT + col4] =
                    *(const float4*)&wbase[(size_t)row * H_FEAT + col4];
            }
        }
        __syncthreads();
        #pragma unroll
        for (int kk = 0; kk < BK; ++kk) {
            ulonglong2 w0 = *(const ulonglong2*)&Ws[kk * H_FEAT + c0];
            ulonglong2 w1 = *(const ulonglong2*)&Ws[kk * H_FEAT + c0 + 4];
            #pragma unroll
            for (int i = 0; i < 8; i++) {
                float a = Xs[(r0 + i) * XS_STRIDE + kk];
                unsigned long long aa = pack2(a, a);
                fma2(acc[i][0], aa, w0.x);
                fma2(acc[i][1], aa, w0.y);
                fma2(acc[i][2], aa, w1.x);
                fma2(acc[i][3], aa, w1.y);
            }
        }
        __syncthreads();
    }

    // -------- ReLU -> Hs --------
    #pragma unroll
    for (int i = 0; i < 8; i++) {
        float h[8];
        unpack2(acc[i][0], h[0], h[1]);
        unpack2(acc[i][1], h[2], h[3]);
        unpack2(acc[i][2], h[4], h[5]);
        unpack2(acc[i][3], h[6], h[7]);
        #pragma unroll
        for (int j = 0; j < 8; j++) h[j] = fmaxf(h[j], 0.0f);
        float* hp = &Hs[(r0 + i) * HS_STRIDE + c0];
        *(float4*)hp       = make_float4(h[0], h[1], h[2], h[3]);
        *(float4*)(hp + 4) = make_float4(h[4], h[5], h[6], h[7]);
    }
    {   // init with layer-2 bias
        ulonglong2 b0 = *(const ulonglong2*)&be2[c0];
        ulonglong2 b1 = *(const ulonglong2*)&be2[c0 + 4];
        #pragma unroll
        for (int i = 0; i < 8; i++) {
            acc[i][0] = b0.x; acc[i][1] = b0.y; acc[i][2] = b1.x; acc[i][3] = b1.y;
        }
    }
    __syncthreads();

    // -------- layer 2: K = 128 from Hs --------
    for (int chunk = 0; chunk < 8; ++chunk) {
        const int koff = chunk * BK;
        #pragma unroll
        for (int t = 0; t < 4; ++t) {
            int q = tid + t * NTHREADS;
            int row = q >> 5, col4 = (q & 31) * 4;
            *(float4*)&Ws[row * H_FEAT + col4] =
                *(const float4*)&We2[(size_t)(koff + row) * H_FEAT + col4];
        }
        __syncthreads();
        #pragma unroll
        for (int kk = 0; kk < BK; ++kk) {
            ulonglong2 w0 = *(const ulonglong2*)&Ws[kk * H_FEAT + c0];
            ulonglong2 w1 = *(const ulonglong2*)&Ws[kk * H_FEAT + c0 + 4];
            #pragma unroll
            for (int i = 0; i < 8; i++) {
                float a = Hs[(r0 + i) * HS_STRIDE + koff + kk];
                unsigned long long aa = pack2(a, a);
                fma2(acc[i][0], aa, w0.x);
                fma2(acc[i][1], aa, w0.y);
                fma2(acc[i][2], aa, w1.x);
                fma2(acc[i][3], aa, w1.y);
            }
        }
        __syncthreads();
    }

    // -------- epilogue: residual write + scatter-add --------
    #pragma unroll
    for (int i = 0; i < 8; i++) {
        const int e = e0 + r0 + i;
        float u[8];
        unpack2(acc[i][0], u[0], u[1]);
        unpack2(acc[i][1], u[2], u[3]);
        unpack2(acc[i][2], u[4], u[5]);
        unpack2(acc[i][3], u[6], u[7]);

        float* aggp = &agg[(size_t)rIdx[r0 + i] * D_FEAT + c0];
        red_add4(aggp,     u[0], u[1], u[2], u[3]);
        red_add4(aggp + 4, u[4], u[5], u[6], u[7]);

        const float4 efa = *(const float4*)&ef[(size_t)e * D_FEAT + c0];
        const float4 efb = *(const float4*)&ef[(size_t)e * D_FEAT + c0 + 4];
        float4 o0 = make_float4(u[0] + efa.x, u[1] + efa.y, u[2] + efa.z, u[3] + efa.w);
        float4 o1 = make_float4(u[4] + efb.x, u[5] + efb.y, u[6] + efb.z, u[7] + efb.w);
        *(float4*)&out_edges[(size_t)e * D_FEAT + c0]     = o0;
        *(float4*)&out_edges[(size_t)e * D_FEAT + c0 + 4] = o1;
    }
}

// ============================================================================
// Node kernel: n_upd = relu([nf, agg] @ Wn1 + bn1) @ Wn2 + bn2
//   out_nodes = nf + n_upd
// ============================================================================
__global__ void __launch_bounds__(NTHREADS, 3)
node_kernel(const float* __restrict__ nf, const float* __restrict__ agg,
            const float* __restrict__ Wn1, const float* __restrict__ bn1,
            const float* __restrict__ Wn2, const float* __restrict__ bn2,
            float* __restrict__ out_nodes)
{
    __shared__ __align__(16) float Xs[TM * XS_STRIDE];
    __shared__ __align__(16) float Ws[BK * H_FEAT];
    __shared__ __align__(16) float Hs[TM * HS_STRIDE];

    const int tid = threadIdx.x;
    const int ty = tid >> 4, tx = tid & 15;
    const int r0 = ty * 8, c0 = tx * 8;
    const int n0 = blockIdx.x * TM;

    unsigned long long acc[8][4];
    {
        ulonglong2 b0 = *(const ulonglong2*)&bn1[c0];
        ulonglong2 b1 = *(const ulonglong2*)&bn1[c0 + 4];
        #pragma unroll
        for (int i = 0; i < 8; i++) {
            acc[i][0] = b0.x; acc[i][1] = b0.y; acc[i][2] = b1.x; acc[i][3] = b1.y;
        }
    }

    // -------- layer 1: K = 256 over [nf | agg], chunks of 16 --------
    for (int chunk = 0; chunk < 16; ++chunk) {
        const int src  = chunk >> 3;   // 0: nf, 1: agg
        const int koff = (chunk & 7) * BK;
        {
            #pragma unroll
            for (int t = 0; t < 2; ++t) {
                int q = tid + t * NTHREADS;
                int row = q >> 2, j4 = (q & 3) * 4;
                int m = n0 + row;
                if (m >= N_NODES) m = N_NODES - 1;   // clamp (writes guarded later)
                const float* base = src ? agg : nf;
                float4 v = *(const float4*)&base[(size_t)m * D_FEAT + koff + j4];
                *(float4*)&Xs[row * XS_STRIDE + j4] = v;
            }
        }
        {
            const float* wbase = Wn1 + (size_t)(src * D_FEAT + koff) * H_FEAT;
            #pragma unroll
            for (int t = 0; t < 4; ++t) {
                int q = tid + t * NTHREADS;
                int row = q >> 5, col4 = (q & 31) * 4;
                *(float4*)&Ws[row * H_FEAT + col4] =
                    *(const float4*)&wbase[(size_t)row * H_FEAT + col4];
            }
        }
        __syncthreads();
        #pragma unroll
        for (int kk = 0; kk < BK; ++kk) {
            ulonglong2 w0 = *(const ulonglong2*)&Ws[kk * H_FEAT + c0];
            ulonglong2 w1 = *(const ulonglong2*)&Ws[kk * H_FEAT + c0 + 4];
            #pragma unroll
            for (int i = 0; i < 8; i++) {
                float a = Xs[(r0 + i) * XS_STRIDE + kk];
                unsigned long long aa = pack2(a, a);
                fma2(acc[i][0], aa, w0.x);
                fma2(acc[i][1], aa, w0.y);
                fma2(acc[i][2], aa, w1.x);
                fma2(acc[i][3], aa, w1.y);
            }
        }
        __syncthreads();
    }

    // -------- ReLU -> Hs --------
    #pragma unroll
    for (int i = 0; i < 8; i++) {
        float h[8];
        unpack2(acc[i][0], h[0], h[1]);
        unpack2(acc[i][1], h[2], h[3]);
        unpack2(acc[i][2], h[4], h[5]);
        unpack2(acc[i][3], h[6], h[7]);
        #pragma unroll
        for (int j = 0; j < 8; j++) h[j] = fmaxf(h[j], 0.0f);
        float* hp = &Hs[(r0 + i) * HS_STRIDE + c0];
        *(float4*)hp       = make_float4(h[0], h[1], h[2], h[3]);
        *(float4*)(hp + 4) = make_float4(h[4], h[5], h[6], h[7]);
    }
    {
        ulonglong2 b0 = *(const ulonglong2*)&bn2[c0];
        ulonglong2 b1 = *(const ulonglong2*)&bn2[c0 + 4];
        #pragma unroll
        for (int i = 0; i < 8; i++) {
            acc[i][0] = b0.x; acc[i][1] = b0.y; acc[i][2] = b1.x; acc[i][3] = b1.y;
        }
    }
    __syncthreads();

    // -------- layer 2: K = 128 from Hs --------
    for (int chunk = 0; chunk < 8; ++chunk) {
        const int koff = chunk * BK;
        #pragma unroll
        for (int t = 0; t < 4; ++t) {
            int q = tid + t * NTHREADS;
            int row = q >> 5, col4 = (q & 31) * 4;
            *(float4*)&Ws[row * H_FEAT + col4] =
                *(const float4*)&Wn2[(size_t)(koff + row) * H_FEAT + col4];
        }
        __syncthreads();
        #pragma unroll
        for (int kk = 0; kk < BK; ++kk) {
            ulonglong2 w0 = *(const ulonglong2*)&Ws[kk * H_FEAT + c0];
            ulonglong2 w1 = *(const ulonglong2*)&Ws[kk * H_FEAT + c0 + 4];
            #pragma unroll
            for (int i = 0; i < 8; i++) {
                float a = Hs[(r0 + i) * HS_STRIDE + koff + kk];
                unsigned long long aa = pack2(a, a);
                fma2(acc[i][0], aa, w0.x);
                fma2(acc[i][1], aa, w0.y);
                fma2(acc[i][2], aa, w1.x);
                fma2(acc[i][3], aa, w1.y);
            }
        }
        __syncthreads();
    }

    // -------- epilogue: residual write (guarded) --------
    #pragma unroll
    for (int i = 0; i < 8; i++) {
        const int m = n0 + r0 + i;
        if (m < N_NODES) {
            float u[8];
            unpack2(acc[i][0], u[0], u[1]);
            unpack2(acc[i][1], u[2], u[3]);
            unpack2(acc[i][2], u[4], u[5]);
            unpack2(acc[i][3], u[6], u[7]);
            const float4 na = *(const float4*)&nf[(size_t)m * D_FEAT + c0];
            const float4 nb = *(const float4*)&nf[(size_t)m * D_FEAT + c0 + 4];
            float4 o0 = make_float4(u[0] + na.x, u[1] + na.y, u[2] + na.z, u[3] + na.w);
            float4 o1 = make_float4(u[4] + nb.x, u[5] + nb.y, u[6] + nb.z, u[7] + nb.w);
            *(float4*)&out_nodes[(size_t)m * D_FEAT + c0]     = o0;
            *(float4*)&out_nodes[(size_t)m * D_FEAT + c0 + 4] = o1;
        }
    }
}

// ============================================================================
extern "C" void kernel_launch(void* const* d_in, const int* in_sizes, int n_in,
                              void* d_out, int out_size)
{
    const float* nf  = (const float*)d_in[0];
    const float* ef  = (const float*)d_in[1];
    const int*   snd = (const int*)  d_in[2];
    const int*   rcv = (const int*)  d_in[3];
    const float* We1 = (const float*)d_in[4];
    const float* be1 = (const float*)d_in[5];
    const float* We2 = (const float*)d_in[6];
    const float* be2 = (const float*)d_in[7];
    const float* Wn1 = (const float*)d_in[8];
    const float* bn1 = (const float*)d_in[9];
    const float* Wn2 = (const float*)d_in[10];
    const float* bn2 = (const float*)d_in[11];

    float* out_nodes = (float*)d_out;                            // [N, D] first
    float* out_edges = (float*)d_out + (size_t)N_NODES * D_FEAT; // [E, D] second

    float* aggp = nullptr;
    cudaGetSymbolAddress((void**)&aggp, g_agg);
    cudaMemsetAsync(aggp, 0, (size_t)N_NODES * D_FEAT * sizeof(float));

    edge_kernel<<<N_EDGES / TM, NTHREADS>>>(nf, ef, snd, rcv,
                                            We1, be1, We2, be2,
                                            out_edges, aggp);
    node_kernel<<<(N_NODES + TM - 1) / TM, NTHREADS>>>(nf, aggp,
                                                       Wn1, bn1, Wn2, bn2,
                                                       out_nodes);
}

// round 6
// speedup vs baseline: 1.4703x; 1.0017x over previous
#include <cuda_runtime.h>
#include <cstdint>

#define D_FEAT   128
#define H_FEAT   128
#define N_NODES  100000
#define N_EDGES  800000

#define TM       64      // rows (edges/nodes) per CTA
#define BK       16      // K-chunk
#define NTHREADS 128     // 16 (tx) x 8 (ty); thread tile = 8 rows x 8 cols
#define XS_STRIDE (BK + 4)      // 20
#define HS_STRIDE (D_FEAT + 4)  // 132

// scatter-sum scratch (51.2 MB). __device__ global: allowed (no alloc).
__device__ float g_agg[(size_t)N_NODES * D_FEAT];

// ---- packed f32x2 helpers (Blackwell FFMA2 path, PTX-only) ----
__device__ __forceinline__ void fma2(unsigned long long &c,
                                     unsigned long long a,
                                     unsigned long long b) {
    asm("fma.rn.f32x2 %0, %1, %2, %3;" : "=l"(c) : "l"(a), "l"(b), "l"(c));
}
__device__ __forceinline__ unsigned long long pack2(float lo, float hi) {
    unsigned long long r;
    asm("mov.b64 %0, {%1, %2};" : "=l"(r) : "f"(lo), "f"(hi));
    return r;
}
__device__ __forceinline__ void unpack2(unsigned long long v, float &lo, float &hi) {
    asm("mov.b64 {%0, %1}, %2;" : "=f"(lo), "=f"(hi) : "l"(v));
}
__device__ __forceinline__ void red_add4(float* p, float a, float b, float c, float d) {
    asm volatile("red.global.add.v4.f32 [%0], {%1, %2, %3, %4};"
                 :: "l"(p), "f"(a), "f"(b), "f"(c), "f"(d) : "memory");
}

// ============================================================================
// Edge kernel: e_upd = relu([nf[s], nf[r], ef] @ We1 + be1) @ We2 + be2
//   out_edges = ef + e_upd ;  red-add e_upd into g_agg[receiver]
// ============================================================================
__global__ void __launch_bounds__(NTHREADS, 3)
edge_kernel(const float* __restrict__ nf, const float* __restrict__ ef,
            const int* __restrict__ snd, const int* __restrict__ rcv,
            const float* __restrict__ We1, const float* __restrict__ be1,
            const float* __restrict__ We2, const float* __restrict__ be2,
            float* __restrict__ out_edges, float* __restrict__ agg)
{
    __shared__ __align__(16) int   sIdx[TM];
    __shared__ __align__(16) int   rIdx[TM];
    __shared__ __align__(16) float Xs[TM * XS_STRIDE];
    __shared__ __align__(16) float Ws[BK * H_FEAT];
    __shared__ __align__(16) float Hs[TM * HS_STRIDE];

    const int tid = threadIdx.x;
    const int ty = tid >> 4, tx = tid & 15;
    const int r0 = ty * 8, c0 = tx * 8;
    const int e0 = blockIdx.x * TM;

    if (tid < TM) { sIdx[tid] = snd[e0 + tid]; rIdx[tid] = rcv[e0 + tid]; }

    unsigned long long acc[8][4];
    {   // init with layer-1 bias
        ulonglong2 b0 = *(const ulonglong2*)&be1[c0];
        ulonglong2 b1 = *(const ulonglong2*)&be1[c0 + 4];
        #pragma unroll
        for (int i = 0; i < 8; i++) {
            acc[i][0] = b0.x; acc[i][1] = b0.y; acc[i][2] = b1.x; acc[i][3] = b1.y;
        }
    }
    __syncthreads();

    // -------- layer 1: K = 384 over 3 gathered sources, chunks of 16 --------
    for (int chunk = 0; chunk < 24; ++chunk) {
        const int src  = chunk >> 3;          // 0: sender nf, 1: receiver nf, 2: ef
        const int koff = (chunk & 7) * BK;
        {   // Xs tile: 64 rows x 16 floats = 256 float4, 2 per thread
            #pragma unroll
            for (int t = 0; t < 2; ++t) {
                int q = tid + t * NTHREADS;
                int row = q >> 2, j4 = (q & 3) * 4;
                size_t grow;
                const float* base;
                if (src == 0)      { grow = (size_t)sIdx[row]; base = nf; }
                else if (src == 1) { grow = (size_t)rIdx[row]; base = nf; }
                else               { grow = (size_t)(e0 + row); base = ef; }
                float4 v = *(const float4*)&base[grow * D_FEAT + koff + j4];
                *(float4*)&Xs[row * XS_STRIDE + j4] = v;
            }
        }
        {   // Ws tile: 16 x 128 = 512 float4, 4 per thread
            const float* wbase = We1 + (size_t)(src * D_FEAT + koff) * H_FEAT;
            #pragma unroll
            for (int t = 0; t < 4; ++t) {
                int q = tid + t * NTHREADS;
                int row = q >> 5, col4 = (q & 31) * 4;
                *(float4*)&Ws[row * H_FEAT + col4] =
                    *(const float4*)&wbase[(size_t)row * H_FEAT + col4];
            }
        }
        __syncthreads();
        #pragma unroll
        for (int kk = 0; kk < BK; ++kk) {
            ulonglong2 w0 = *(const ulonglong2*)&Ws[kk * H_FEAT + c0];
            ulonglong2 w1 = *(const ulonglong2*)&Ws[kk * H_FEAT + c0 + 4];
            #pragma unroll
            for (int i = 0; i < 8; i++) {
                float a = Xs[(r0 + i) * XS_STRIDE + kk];
                unsigned long long aa = pack2(a, a);
                fma2(acc[i][0], aa, w0.x);
                fma2(acc[i][1], aa, w0.y);
                fma2(acc[i][2], aa, w1.x);
                fma2(acc[i][3], aa, w1.y);
            }
        }
        __syncthreads();
    }

    // -------- ReLU -> Hs --------
    #pragma unroll
    for (int i = 0; i < 8; i++) {
        float h[8];
        unpack2(acc[i][0], h[0], h[1]);
        unpack2(acc[i][1], h[2], h[3]);
        unpack2(acc[i][2], h[4], h[5]);
        unpack2(acc[i][3], h[6], h[7]);
        #pragma unroll
        for (int j = 0; j < 8; j++) h[j] = fmaxf(h[j], 0.0f);
        float* hp = &Hs[(r0 + i) * HS_STRIDE + c0];
        *(float4*)hp       = make_float4(h[0], h[1], h[2], h[3]);
        *(float4*)(hp + 4) = make_float4(h[4], h[5], h[6], h[7]);
    }
    {   // init with layer-2 bias
        ulonglong2 b0 = *(const ulonglong2*)&be2[c0];
        ulonglong2 b1 = *(const ulonglong2*)&be2[c0 + 4];
        #pragma unroll
        for (int i = 0; i < 8; i++) {
            acc[i][0] = b0.x; acc[i][1] = b0.y; acc[i][2] = b1.x; acc[i][3] = b1.y;
        }
    }
    __syncthreads();

    // -------- layer 2: K = 128 from Hs --------
    for (int chunk = 0; chunk < 8; ++chunk) {
        const int koff = chunk * BK;
        #pragma unroll
        for (int t = 0; t < 4; ++t) {
            int q = tid + t * NTHREADS;
            int row = q >> 5, col4 = (q & 31) * 4;
            *(float4*)&Ws[row * H_FEAT + col4] =
                *(const float4*)&We2[(size_t)(koff + row) * H_FEAT + col4];
        }
        __syncthreads();
        #pragma unroll
        for (int kk = 0; kk < BK; ++kk) {
            ulonglong2 w0 = *(const ulonglong2*)&Ws[kk * H_FEAT + c0];
            ulonglong2 w1 = *(const ulonglong2*)&Ws[kk * H_FEAT + c0 + 4];
            #pragma unroll
            for (int i = 0; i < 8; i++) {
                float a = Hs[(r0 + i) * HS_STRIDE + koff + kk];
                unsigned long long aa = pack2(a, a);
                fma2(acc[i][0], aa, w0.x);
                fma2(acc[i][1], aa, w0.y);
                fma2(acc[i][2], aa, w1.x);
                fma2(acc[i][3], aa, w1.y);
            }
        }
        __syncthreads();
    }

    // -------- epilogue: residual write + scatter-add --------
    #pragma unroll
    for (int i = 0; i < 8; i++) {
        const int e = e0 + r0 + i;
        float u[8];
        unpack2(acc[i][0], u[0], u[1]);
        unpack2(acc[i][1], u[2], u[3]);
        unpack2(acc[i][2], u[4], u[5]);
        unpack2(acc[i][3], u[6], u[7]);

        float* aggp = &agg[(size_t)rIdx[r0 + i] * D_FEAT + c0];
        red_add4(aggp,     u[0], u[1], u[2], u[3]);
        red_add4(aggp + 4, u[4], u[5], u[6], u[7]);

        const float4 efa = *(const float4*)&ef[(size_t)e * D_FEAT + c0];
        const float4 efb = *(const float4*)&ef[(size_t)e * D_FEAT + c0 + 4];
        float4 o0 = make_float4(u[0] + efa.x, u[1] + efa.y, u[2] + efa.z, u[3] + efa.w);
        float4 o1 = make_float4(u[4] + efb.x, u[5] + efb.y, u[6] + efb.z, u[7] + efb.w);
        *(float4*)&out_edges[(size_t)e * D_FEAT + c0]     = o0;
        *(float4*)&out_edges[(size_t)e * D_FEAT + c0 + 4] = o1;
    }
}

// ============================================================================
// Node kernel: n_upd = relu([nf, agg] @ Wn1 + bn1) @ Wn2 + bn2
//   out_nodes = nf + n_upd
// ============================================================================
__global__ void __launch_bounds__(NTHREADS, 3)
node_kernel(const float* __restrict__ nf, const float* __restrict__ agg,
            const float* __restrict__ Wn1, const float* __restrict__ bn1,
            const float* __restrict__ Wn2, const float* __restrict__ bn2,
            float* __restrict__ out_nodes)
{
    __shared__ __align__(16) float Xs[TM * XS_STRIDE];
    __shared__ __align__(16) float Ws[BK * H_FEAT];
    __shared__ __align__(16) float Hs[TM * HS_STRIDE];

    const int tid = threadIdx.x;
    const int ty = tid >> 4, tx = tid & 15;
    const int r0 = ty * 8, c0 = tx * 8;
    const int n0 = blockIdx.x * TM;

    unsigned long long acc[8][4];
    {
        ulonglong2 b0 = *(const ulonglong2*)&bn1[c0];
        ulonglong2 b1 = *(const ulonglong2*)&bn1[c0 + 4];
        #pragma unroll
        for (int i = 0; i < 8; i++) {
            acc[i][0] = b0.x; acc[i][1] = b0.y; acc[i][2] = b1.x; acc[i][3] = b1.y;
        }
    }

    // -------- layer 1: K = 256 over [nf | agg], chunks of 16 --------
    for (int chunk = 0; chunk < 16; ++chunk) {
        const int src  = chunk >> 3;   // 0: nf, 1: agg
        const int koff = (chunk & 7) * BK;
        {
            #pragma unroll
            for (int t = 0; t < 2; ++t) {
                int q = tid + t * NTHREADS;
                int row = q >> 2, j4 = (q & 3) * 4;
                int m = n0 + row;
                if (m >= N_NODES) m = N_NODES - 1;   // clamp (writes guarded later)
                const float* base = src ? agg : nf;
                float4 v = *(const float4*)&base[(size_t)m * D_FEAT + koff + j4];
                *(float4*)&Xs[row * XS_STRIDE + j4] = v;
            }
        }
        {
            const float* wbase = Wn1 + (size_t)(src * D_FEAT + koff) * H_FEAT;
            #pragma unroll
            for (int t = 0; t < 4; ++t) {
                int q = tid + t * NTHREADS;
                int row = q >> 5, col4 = (q & 31) * 4;
                *(float4*)&Ws[row * H_FEAT + col4] =
                    *(const float4*)&wbase[(size_t)row * H_FEAT + col4];
            }
        }
        __syncthreads();
        #pragma unroll
        for (int kk = 0; kk < BK; ++kk) {
            ulonglong2 w0 = *(const ulonglong2*)&Ws[kk * H_FEAT + c0];
            ulonglong2 w1 = *(const ulonglong2*)&Ws[kk * H_FEAT + c0 + 4];
            #pragma unroll
            for (int i = 0; i < 8; i++) {
                float a = Xs[(r0 + i) * XS_STRIDE + kk];
                unsigned long long aa = pack2(a, a);
                fma2(acc[i][0], aa, w0.x);
                fma2(acc[i][1], aa, w0.y);
                fma2(acc[i][2], aa, w1.x);
                fma2(acc[i][3], aa, w1.y);
            }
        }
        __syncthreads();
    }

    // -------- ReLU -> Hs --------
    #pragma unroll
    for (int i = 0; i < 8; i++) {
        float h[8];
        unpack2(acc[i][0], h[0], h[1]);
        unpack2(acc[i][1], h[2], h[3]);
        unpack2(acc[i][2], h[4], h[5]);
        unpack2(acc[i][3], h[6], h[7]);
        #pragma unroll
        for (int j = 0; j < 8; j++) h[j] = fmaxf(h[j], 0.0f);
        float* hp = &Hs[(r0 + i) * HS_STRIDE + c0];
        *(float4*)hp       = make_float4(h[0], h[1], h[2], h[3]);
        *(float4*)(hp + 4) = make_float4(h[4], h[5], h[6], h[7]);
    }
    {
        ulonglong2 b0 = *(const ulonglong2*)&bn2[c0];
        ulonglong2 b1 = *(const ulonglong2*)&bn2[c0 + 4];
        #pragma unroll
        for (int i = 0; i < 8; i++) {
            acc[i][0] = b0.x; acc[i][1] = b0.y; acc[i][2] = b1.x; acc[i][3] = b1.y;
        }
    }
    __syncthreads();

    // -------- layer 2: K = 128 from Hs --------
    for (int chunk = 0; chunk < 8; ++chunk) {
        const int koff = chunk * BK;
        #pragma unroll
        for (int t = 0; t < 4; ++t) {
            int q = tid + t * NTHREADS;
            int row = q >> 5, col4 = (q & 31) * 4;
            *(float4*)&Ws[row * H_FEAT + col4] =
                *(const float4*)&Wn2[(size_t)(koff + row) * H_FEAT + col4];
        }
        __syncthreads();
        #pragma unroll
        for (int kk = 0; kk < BK; ++kk) {
            ulonglong2 w0 = *(const ulonglong2*)&Ws[kk * H_FEAT + c0];
            ulonglong2 w1 = *(const ulonglong2*)&Ws[kk * H_FEAT + c0 + 4];
            #pragma unroll
            for (int i = 0; i < 8; i++) {
                float a = Hs[(r0 + i) * HS_STRIDE + koff + kk];
                unsigned long long aa = pack2(a, a);
                fma2(acc[i][0], aa, w0.x);
                fma2(acc[i][1], aa, w0.y);
                fma2(acc[i][2], aa, w1.x);
                fma2(acc[i][3], aa, w1.y);
            }
        }
        __syncthreads();
    }

    // -------- epilogue: residual write (guarded) --------
    #pragma unroll
    for (int i = 0; i < 8; i++) {
        const int m = n0 + r0 + i;
        if (m < N_NODES) {
            float u[8];
            unpack2(acc[i][0], u[0], u[1]);
            unpack2(acc[i][1], u[2], u[3]);
            unpack2(acc[i][2], u[4], u[5]);
            unpack2(acc[i][3], u[6], u[7]);
            const float4 na = *(const float4*)&nf[(size_t)m * D_FEAT + c0];
            const float4 nb = *(const float4*)&nf[(size_t)m * D_FEAT + c0 + 4];
            float4 o0 = make_float4(u[0] + na.x, u[1] + na.y, u[2] + na.z, u[3] + na.w);
            float4 o1 = make_float4(u[4] + nb.x, u[5] + nb.y, u[6] + nb.z, u[7] + nb.w);
            *(float4*)&out_nodes[(size_t)m * D_FEAT + c0]     = o0;
            *(float4*)&out_nodes[(size_t)m * D_FEAT + c0 + 4] = o1;
        }
    }
}

// ============================================================================
extern "C" void kernel_launch(void* const* d_in, const int* in_sizes, int n_in,
                              void* d_out, int out_size)
{
    const float* nf  = (const float*)d_in[0];
    const float* ef  = (const float*)d_in[1];
    const int*   snd = (const int*)  d_in[2];
    const int*   rcv = (const int*)  d_in[3];
    const float* We1 = (const float*)d_in[4];
    const float* be1 = (const float*)d_in[5];
    const float* We2 = (const float*)d_in[6];
    const float* be2 = (const float*)d_in[7];
    const float* Wn1 = (const float*)d_in[8];
    const float* bn1 = (const float*)d_in[9];
    const float* Wn2 = (const float*)d_in[10];
    const float* bn2 = (const float*)d_in[11];

    float* out_nodes = (float*)d_out;                            // [N, D] first
    float* out_edges = (float*)d_out + (size_t)N_NODES * D_FEAT; // [E, D] second

    float* aggp = nullptr;
    cudaGetSymbolAddress((void**)&aggp, g_agg);
    cudaMemsetAsync(aggp, 0, (size_t)N_NODES * D_FEAT * sizeof(float));

    edge_kernel<<<N_EDGES / TM, NTHREADS>>>(nf, ef, snd, rcv,
                                            We1, be1, We2, be2,
                                            out_edges, aggp);
    node_kernel<<<(N_NODES + TM - 1) / TM, NTHREADS>>>(nf, aggp,
                                                       Wn1, bn1, Wn2, bn2,
                                                       out_nodes);
}

// round 7
// speedup vs baseline: 1.4709x; 1.0004x over previous
#include <cuda_runtime.h>
#include <cstdint>

#define D_FEAT   128
#define H_FEAT   128
#define N_NODES  100000
#define N_EDGES  800000

#define TM       64      // rows (edges/nodes) per CTA
#define BK       16      // K-chunk
#define NTHREADS 128     // 16 (tx) x 8 (ty); thread tile = 8 rows x 8 cols
#define XS_STRIDE (BK + 4)      // 20
#define HS_STRIDE (D_FEAT + 4)  // 132

// scatter-sum scratch (51.2 MB). __device__ global: allowed (no alloc).
__device__ float g_agg[(size_t)N_NODES * D_FEAT];

// ---- packed f32x2 helpers (Blackwell FFMA2 path, PTX-only) ----
__device__ __forceinline__ void fma2(unsigned long long &c,
                                     unsigned long long a,
                                     unsigned long long b) {
    asm("fma.rn.f32x2 %0, %1, %2, %3;" : "=l"(c) : "l"(a), "l"(b), "l"(c));
}
__device__ __forceinline__ unsigned long long pack2(float lo, float hi) {
    unsigned long long r;
    asm("mov.b64 %0, {%1, %2};" : "=l"(r) : "f"(lo), "f"(hi));
    return r;
}
__device__ __forceinline__ void unpack2(unsigned long long v, float &lo, float &hi) {
    asm("mov.b64 {%0, %1}, %2;" : "=f"(lo), "=f"(hi) : "l"(v));
}
__device__ __forceinline__ void red_add4(float* p, float a, float b, float c, float d) {
    asm volatile("red.global.add.v4.f32 [%0], {%1, %2, %3, %4};"
                 :: "l"(p), "f"(a), "f"(b), "f"(c), "f"(d) : "memory");
}

// ============================================================================
// Edge kernel: e_upd = relu([nf[s], nf[r], ef] @ We1 + be1) @ We2 + be2
//   out_edges = ef + e_upd ;  red-add e_upd into g_agg[receiver]
// ============================================================================
__global__ void __launch_bounds__(NTHREADS, 3)
edge_kernel(const float* __restrict__ nf, const float* __restrict__ ef,
            const int* __restrict__ snd, const int* __restrict__ rcv,
            const float* __restrict__ We1, const float* __restrict__ be1,
            const float* __restrict__ We2, const float* __restrict__ be2,
            float* __restrict__ out_edges, float* __restrict__ agg)
{
    __shared__ __align__(16) int   sIdx[TM];
    __shared__ __align__(16) int   rIdx[TM];
    __shared__ __align__(16) float Xs[TM * XS_STRIDE];
    __shared__ __align__(16) float Ws[BK * H_FEAT];
    __shared__ __align__(16) float Hs[TM * HS_STRIDE];

    const int tid = threadIdx.x;
    const int ty = tid >> 4, tx = tid & 15;
    const int r0 = ty * 8, c0 = tx * 8;
    const int e0 = blockIdx.x * TM;

    if (tid < TM) { sIdx[tid] = snd[e0 + tid]; rIdx[tid] = rcv[e0 + tid]; }

    unsigned long long acc[8][4];
    {   // init with layer-1 bias
        ulonglong2 b0 = *(const ulonglong2*)&be1[c0];
        ulonglong2 b1 = *(const ulonglong2*)&be1[c0 + 4];
        #pragma unroll
        for (int i = 0; i < 8; i++) {
            acc[i][0] = b0.x; acc[i][1] = b0.y; acc[i][2] = b1.x; acc[i][3] = b1.y;
        }
    }
    __syncthreads();

    // -------- layer 1: K = 384 over 3 gathered sources, chunks of 16 --------
    for (int chunk = 0; chunk < 24; ++chunk) {
        const int src  = chunk >> 3;          // 0: sender nf, 1: receiver nf, 2: ef
        const int koff = (chunk & 7) * BK;
        {   // Xs tile: 64 rows x 16 floats = 256 float4, 2 per thread
            #pragma unroll
            for (int t = 0; t < 2; ++t) {
                int q = tid + t * NTHREADS;
                int row = q >> 2, j4 = (q & 3) * 4;
                size_t grow;
                const float* base;
                if (src == 0)      { grow = (size_t)sIdx[row]; base = nf; }
                else if (src == 1) { grow = (size_t)rIdx[row]; base = nf; }
                else               { grow = (size_t)(e0 + row); base = ef; }
                float4 v = *(const float4*)&base[grow * D_FEAT + koff + j4];
                *(float4*)&Xs[row * XS_STRIDE + j4] = v;
            }
        }
        {   // Ws tile: 16 x 128 = 512 float4, 4 per thread
            const float* wbase = We1 + (size_t)(src * D_FEAT + koff) * H_FEAT;
            #pragma unroll
            for (int t = 0; t < 4; ++t) {
                int q = tid + t * NTHREADS;
                int row = q >> 5, col4 = (q & 31) * 4;
                *(float4*)&Ws[row * H_FEAT + col4] =
                    *(const float4*)&wbase[(size_t)row * H_FEAT + col4];
            }
        }
        __syncthreads();
        #pragma unroll
        for (int kk = 0; kk < BK; ++kk) {
            ulonglong2 w0 = *(const ulonglong2*)&Ws[kk * H_FEAT + c0];
            ulonglong2 w1 = *(const ulonglong2*)&Ws[kk * H_FEAT + c0 + 4];
            #pragma unroll
            for (int i = 0; i < 8; i++) {
                float a = Xs[(r0 + i) * XS_STRIDE + kk];
                unsigned long long aa = pack2(a, a);
                fma2(acc[i][0], aa, w0.x);
                fma2(acc[i][1], aa, w0.y);
                fma2(acc[i][2], aa, w1.x);
                fma2(acc[i][3], aa, w1.y);
            }
        }
        __syncthreads();
    }

    // -------- ReLU -> Hs --------
    #pragma unroll
    for (int i = 0; i < 8; i++) {
        float h[8];
        unpack2(acc[i][0], h[0], h[1]);
        unpack2(acc[i][1], h[2], h[3]);
        unpack2(acc[i][2], h[4], h[5]);
        unpack2(acc[i][3], h[6], h[7]);
        #pragma unroll
        for (int j = 0; j < 8; j++) h[j] = fmaxf(h[j], 0.0f);
        float* hp = &Hs[(r0 + i) * HS_STRIDE + c0];
        *(float4*)hp       = make_float4(h[0], h[1], h[2], h[3]);
        *(float4*)(hp + 4) = make_float4(h[4], h[5], h[6], h[7]);
    }
    {   // init with layer-2 bias
        ulonglong2 b0 = *(const ulonglong2*)&be2[c0];
        ulonglong2 b1 = *(const ulonglong2*)&be2[c0 + 4];
        #pragma unroll
        for (int i = 0; i < 8; i++) {
            acc[i][0] = b0.x; acc[i][1] = b0.y; acc[i][2] = b1.x; acc[i][3] = b1.y;
        }
    }
    __syncthreads();

    // -------- layer 2: K = 128 from Hs --------
    for (int chunk = 0; chunk < 8; ++chunk) {
        const int koff = chunk * BK;
        #pragma unroll
        for (int t = 0; t < 4; ++t) {
            int q = tid + t * NTHREADS;
            int row = q >> 5, col4 = (q & 31) * 4;
            *(float4*)&Ws[row * H_FEAT + col4] =
                *(const float4*)&We2[(size_t)(koff + row) * H_FEAT + col4];
        }
        __syncthreads();
        #pragma unroll
        for (int kk = 0; kk < BK; ++kk) {
            ulonglong2 w0 = *(const ulonglong2*)&Ws[kk * H_FEAT + c0];
            ulonglong2 w1 = *(const ulonglong2*)&Ws[kk * H_FEAT + c0 + 4];
            #pragma unroll
            for (int i = 0; i < 8; i++) {
                float a = Hs[(r0 + i) * HS_STRIDE + koff + kk];
                unsigned long long aa = pack2(a, a);
                fma2(acc[i][0], aa, w0.x);
                fma2(acc[i][1], aa, w0.y);
                fma2(acc[i][2], aa, w1.x);
                fma2(acc[i][3], aa, w1.y);
            }
        }
        __syncthreads();
    }

    // -------- epilogue: residual write + scatter-add --------
    #pragma unroll
    for (int i = 0; i < 8; i++) {
        const int e = e0 + r0 + i;
        float u[8];
        unpack2(acc[i][0], u[0], u[1]);
        unpack2(acc[i][1], u[2], u[3]);
        unpack2(acc[i][2], u[4], u[5]);
        unpack2(acc[i][3], u[6], u[7]);

        float* aggp = &agg[(size_t)rIdx[r0 + i] * D_FEAT + c0];
        red_add4(aggp,     u[0], u[1], u[2], u[3]);
        red_add4(aggp + 4, u[4], u[5], u[6], u[7]);

        const float4 efa = *(const float4*)&ef[(size_t)e * D_FEAT + c0];
        const float4 efb = *(const float4*)&ef[(size_t)e * D_FEAT + c0 + 4];
        float4 o0 = make_float4(u[0] + efa.x, u[1] + efa.y, u[2] + efa.z, u[3] + efa.w);
        float4 o1 = make_float4(u[4] + efb.x, u[5] + efb.y, u[6] + efb.z, u[7] + efb.w);
        *(float4*)&out_edges[(size_t)e * D_FEAT + c0]     = o0;
        *(float4*)&out_edges[(size_t)e * D_FEAT + c0 + 4] = o1;
    }
}

// ============================================================================
// Node kernel: n_upd = relu([nf, agg] @ Wn1 + bn1) @ Wn2 + bn2
//   out_nodes = nf + n_upd
// ============================================================================
__global__ void __launch_bounds__(NTHREADS, 3)
node_kernel(const float* __restrict__ nf, const float* __restrict__ agg,
            const float* __restrict__ Wn1, const float* __restrict__ bn1,
            const float* __restrict__ Wn2, const float* __restrict__ bn2,
            float* __restrict__ out_nodes)
{
    __shared__ __align__(16) float Xs[TM * XS_STRIDE];
    __shared__ __align__(16) float Ws[BK * H_FEAT];
    __shared__ __align__(16) float Hs[TM * HS_STRIDE];

    const int tid = threadIdx.x;
    const int ty = tid >> 4, tx = tid & 15;
    const int r0 = ty * 8, c0 = tx * 8;
    const int n0 = blockIdx.x * TM;

    unsigned long long acc[8][4];
    {
        ulonglong2 b0 = *(const ulonglong2*)&bn1[c0];
        ulonglong2 b1 = *(const ulonglong2*)&bn1[c0 + 4];
        #pragma unroll
        for (int i = 0; i < 8; i++) {
            acc[i][0] = b0.x; acc[i][1] = b0.y; acc[i][2] = b1.x; acc[i][3] = b1.y;
        }
    }

    // -------- layer 1: K = 256 over [nf | agg], chunks of 16 --------
    for (int chunk = 0; chunk < 16; ++chunk) {
        const int src  = chunk >> 3;   // 0: nf, 1: agg
        const int koff = (chunk & 7) * BK;
        {
            #pragma unroll
            for (int t = 0; t < 2; ++t) {
                int q = tid + t * NTHREADS;
                int row = q >> 2, j4 = (q & 3) * 4;
                int m = n0 + row;
                if (m >= N_NODES) m = N_NODES - 1;   // clamp (writes guarded later)
                const float* base = src ? agg : nf;
                float4 v = *(const float4*)&base[(size_t)m * D_FEAT + koff + j4];
                *(float4*)&Xs[row * XS_STRIDE + j4] = v;
            }
        }
        {
            const float* wbase = Wn1 + (size_t)(src * D_FEAT + koff) * H_FEAT;
            #pragma unroll
            for (int t = 0; t < 4; ++t) {
                int q = tid + t * NTHREADS;
                int row = q >> 5, col4 = (q & 31) * 4;
                *(float4*)&Ws[row * H_FEAT + col4] =
                    *(const float4*)&wbase[(size_t)row * H_FEAT + col4];
            }
        }
        __syncthreads();
        #pragma unroll
        for (int kk = 0; kk < BK; ++kk) {
            ulonglong2 w0 = *(const ulonglong2*)&Ws[kk * H_FEAT + c0];
            ulonglong2 w1 = *(const ulonglong2*)&Ws[kk * H_FEAT + c0 + 4];
            #pragma unroll
            for (int i = 0; i < 8; i++) {
                float a = Xs[(r0 + i) * XS_STRIDE + kk];
                unsigned long long aa = pack2(a, a);
                fma2(acc[i][0], aa, w0.x);
                fma2(acc[i][1], aa, w0.y);
                fma2(acc[i][2], aa, w1.x);
                fma2(acc[i][3], aa, w1.y);
            }
        }
        __syncthreads();
    }

    // -------- ReLU -> Hs --------
    #pragma unroll
    for (int i = 0; i < 8; i++) {
        float h[8];
        unpack2(acc[i][0], h[0], h[1]);
        unpack2(acc[i][1], h[2], h[3]);
        unpack2(acc[i][2], h[4], h[5]);
        unpack2(acc[i][3], h[6], h[7]);
        #pragma unroll
        for (int j = 0; j < 8; j++) h[j] = fmaxf(h[j], 0.0f);
        float* hp = &Hs[(r0 + i) * HS_STRIDE + c0];
        *(float4*)hp       = make_float4(h[0], h[1], h[2], h[3]);
        *(float4*)(hp + 4) = make_float4(h[4], h[5], h[6], h[7]);
    }
    {
        ulonglong2 b0 = *(const ulonglong2*)&bn2[c0];
        ulonglong2 b1 = *(const ulonglong2*)&bn2[c0 + 4];
        #pragma unroll
        for (int i = 0; i < 8; i++) {
            acc[i][0] = b0.x; acc[i][1] = b0.y; acc[i][2] = b1.x; acc[i][3] = b1.y;
        }
    }
    __syncthreads();

    // -------- layer 2: K = 128 from Hs --------
    for (int chunk = 0; chunk < 8; ++chunk) {
        const int koff = chunk * BK;
        #pragma unroll
        for (int t = 0; t < 4; ++t) {
            int q = tid + t * NTHREADS;
            int row = q >> 5, col4 = (q & 31) * 4;
            *(float4*)&Ws[row * H_FEAT + col4] =
                *(const float4*)&Wn2[(size_t)(koff + row) * H_FEAT + col4];
        }
        __syncthreads();
        #pragma unroll
        for (int kk = 0; kk < BK; ++kk) {
            ulonglong2 w0 = *(const ulonglong2*)&Ws[kk * H_FEAT + c0];
            ulonglong2 w1 = *(const ulonglong2*)&Ws[kk * H_FEAT + c0 + 4];
            #pragma unroll
            for (int i = 0; i < 8; i++) {
                float a = Hs[(r0 + i) * HS_STRIDE + koff + kk];
                unsigned long long aa = pack2(a, a);
                fma2(acc[i][0], aa, w0.x);
                fma2(acc[i][1], aa, w0.y);
                fma2(acc[i][2], aa, w1.x);
                fma2(acc[i][3], aa, w1.y);
            }
        }
        __syncthreads();
    }

    // -------- epilogue: residual write (guarded) --------
    #pragma unroll
    for (int i = 0; i < 8; i++) {
        const int m = n0 + r0 + i;
        if (m < N_NODES) {
            float u[8];
            unpack2(acc[i][0], u[0], u[1]);
            unpack2(acc[i][1], u[2], u[3]);
            unpack2(acc[i][2], u[4], u[5]);
            unpack2(acc[i][3], u[6], u[7]);
            const float4 na = *(const float4*)&nf[(size_t)m * D_FEAT + c0];
            const float4 nb = *(const float4*)&nf[(size_t)m * D_FEAT + c0 + 4];
            float4 o0 = make_float4(u[0] + na.x, u[1] + na.y, u[2] + na.z, u[3] + na.w);
            float4 o1 = make_float4(u[4] + nb.x, u[5] + nb.y, u[6] + nb.z, u[7] + nb.w);
            *(float4*)&out_nodes[(size_t)m * D_FEAT + c0]     = o0;
            *(float4*)&out_nodes[(size_t)m * D_FEAT + c0 + 4] = o1;
        }
    }
}

// ============================================================================
extern "C" void kernel_launch(void* const* d_in, const int* in_sizes, int n_in,
                              void* d_out, int out_size)
{
    const float* nf  = (const float*)d_in[0];
    const float* ef  = (const float*)d_in[1];
    const int*   snd = (const int*)  d_in[2];
    const int*   rcv = (const int*)  d_in[3];
    const float* We1 = (const float*)d_in[4];
    const float* be1 = (const float*)d_in[5];
    const float* We2 = (const float*)d_in[6];
    const float* be2 = (const float*)d_in[7];
    const float* Wn1 = (const float*)d_in[8];
    const float* bn1 = (const float*)d_in[9];
    const float* Wn2 = (const float*)d_in[10];
    const float* bn2 = (const float*)d_in[11];

    float* out_nodes = (float*)d_out;                            // [N, D] first
    float* out_edges = (float*)d_out + (size_t)N_NODES * D_FEAT; // [E, D] second

    float* aggp = nullptr;
    cudaGetSymbolAddress((void**)&aggp, g_agg);
    cudaMemsetAsync(aggp, 0, (size_t)N_NODES * D_FEAT * sizeof(float));

    edge_kernel<<<N_EDGES / TM, NTHREADS>>>(nf, ef, snd, rcv,
                                            We1, be1, We2, be2,
                                            out_edges, aggp);
    node_kernel<<<(N_NODES + TM - 1) / TM, NTHREADS>>>(nf, aggp,
                                                       Wn1, bn1, Wn2, bn2,
                                                       out_nodes);
}

// round 8
// speedup vs baseline: 1.4709x; 1.0000x over previous
#include <cuda_runtime.h>
#include <cstdint>

#define D_FEAT   128
#define H_FEAT   128
#define N_NODES  100000
#define N_EDGES  800000

#define TM       64      // rows (edges/nodes) per CTA
#define BK       16      // K-chunk
#define NTHREADS 128     // 16 (tx) x 8 (ty); thread tile = 8 rows x 8 cols
#define XS_STRIDE (BK + 4)      // 20
#define HS_STRIDE (D_FEAT + 4)  // 132

// scatter-sum scratch (51.2 MB). __device__ global: allowed (no alloc).
__device__ float g_agg[(size_t)N_NODES * D_FEAT];

// ---- packed f32x2 helpers (Blackwell FFMA2 path, PTX-only) ----
__device__ __forceinline__ void fma2(unsigned long long &c,
                                     unsigned long long a,
                                     unsigned long long b) {
    asm("fma.rn.f32x2 %0, %1, %2, %3;" : "=l"(c) : "l"(a), "l"(b), "l"(c));
}
__device__ __forceinline__ unsigned long long pack2(float lo, float hi) {
    unsigned long long r;
    asm("mov.b64 %0, {%1, %2};" : "=l"(r) : "f"(lo), "f"(hi));
    return r;
}
__device__ __forceinline__ void unpack2(unsigned long long v, float &lo, float &hi) {
    asm("mov.b64 {%0, %1}, %2;" : "=f"(lo), "=f"(hi) : "l"(v));
}
__device__ __forceinline__ void red_add4(float* p, float a, float b, float c, float d) {
    asm volatile("red.global.add.v4.f32 [%0], {%1, %2, %3, %4};"
                 :: "l"(p), "f"(a), "f"(b), "f"(c), "f"(d) : "memory");
}

// ============================================================================
// Edge kernel: e_upd = relu([nf[s], nf[r], ef] @ We1 + be1) @ We2 + be2
//   out_edges = ef + e_upd ;  red-add e_upd into g_agg[receiver]
// ============================================================================
__global__ void __launch_bounds__(NTHREADS, 3)
edge_kernel(const float* __restrict__ nf, const float* __restrict__ ef,
            const int* __restrict__ snd, const int* __restrict__ rcv,
            const float* __restrict__ We1, const float* __restrict__ be1,
            const float* __restrict__ We2, const float* __restrict__ be2,
            float* __restrict__ out_edges, float* __restrict__ agg)
{
    __shared__ __align__(16) int   sIdx[TM];
    __shared__ __align__(16) int   rIdx[TM];
    __shared__ __align__(16) float Xs[TM * XS_STRIDE];
    __shared__ __align__(16) float Ws[BK * H_FEAT];
    __shared__ __align__(16) float Hs[TM * HS_STRIDE];

    const int tid = threadIdx.x;
    const int ty = tid >> 4, tx = tid & 15;
    const int r0 = ty * 8, c0 = tx * 8;
    const int e0 = blockIdx.x * TM;

    if (tid < TM) { sIdx[tid] = snd[e0 + tid]; rIdx[tid] = rcv[e0 + tid]; }

    unsigned long long acc[8][4];
    {   // init with layer-1 bias
        ulonglong2 b0 = *(const ulonglong2*)&be1[c0];
        ulonglong2 b1 = *(const ulonglong2*)&be1[c0 + 4];
        #pragma unroll
        for (int i = 0; i < 8; i++) {
            acc[i][0] = b0.x; acc[i][1] = b0.y; acc[i][2] = b1.x; acc[i][3] = b1.y;
        }
    }
    __syncthreads();

    // -------- layer 1: K = 384 over 3 gathered sources, chunks of 16 --------
    for (int chunk = 0; chunk < 24; ++chunk) {
        const int src  = chunk >> 3;          // 0: sender nf, 1: receiver nf, 2: ef
        const int koff = (chunk & 7) * BK;
        {   // Xs tile: 64 rows x 16 floats = 256 float4, 2 per thread
            #pragma unroll
            for (int t = 0; t < 2; ++t) {
                int q = tid + t * NTHREADS;
                int row = q >> 2, j4 = (q & 3) * 4;
                size_t grow;
                const float* base;
                if (src == 0)      { grow = (size_t)sIdx[row]; base = nf; }
                else if (src == 1) { grow = (size_t)rIdx[row]; base = nf; }
                else               { grow = (size_t)(e0 + row); base = ef; }
                float4 v = *(const float4*)&base[grow * D_FEAT + koff + j4];
                *(float4*)&Xs[row * XS_STRIDE + j4] = v;
            }
        }
        {   // Ws tile: 16 x 128 = 512 float4, 4 per thread
            const float* wbase = We1 + (size_t)(src * D_FEAT + koff) * H_FEAT;
            #pragma unroll
            for (int t = 0; t < 4; ++t) {
                int q = tid + t * NTHREADS;
                int row = q >> 5, col4 = (q & 31) * 4;
                *(float4*)&Ws[row * H_FEAT + col4] =
                    *(const float4*)&wbase[(size_t)row * H_FEAT + col4];
            }
        }
        __syncthreads();
        #pragma unroll
        for (int kk = 0; kk < BK; ++kk) {
            ulonglong2 w0 = *(const ulonglong2*)&Ws[kk * H_FEAT + c0];
            ulonglong2 w1 = *(const ulonglong2*)&Ws[kk * H_FEAT + c0 + 4];
            #pragma unroll
            for (int i = 0; i < 8; i++) {
                float a = Xs[(r0 + i) * XS_STRIDE + kk];
                unsigned long long aa = pack2(a, a);
                fma2(acc[i][0], aa, w0.x);
                fma2(acc[i][1], aa, w0.y);
                fma2(acc[i][2], aa, w1.x);
                fma2(acc[i][3], aa, w1.y);
            }
        }
        __syncthreads();
    }

    // -------- ReLU -> Hs --------
    #pragma unroll
    for (int i = 0; i < 8; i++) {
        float h[8];
        unpack2(acc[i][0], h[0], h[1]);
        unpack2(acc[i][1], h[2], h[3]);
        unpack2(acc[i][2], h[4], h[5]);
        unpack2(acc[i][3], h[6], h[7]);
        #pragma unroll
        for (int j = 0; j < 8; j++) h[j] = fmaxf(h[j], 0.0f);
        float* hp = &Hs[(r0 + i) * HS_STRIDE + c0];
        *(float4*)hp       = make_float4(h[0], h[1], h[2], h[3]);
        *(float4*)(hp + 4) = make_float4(h[4], h[5], h[6], h[7]);
    }
    {   // init with layer-2 bias
        ulonglong2 b0 = *(const ulonglong2*)&be2[c0];
        ulonglong2 b1 = *(const ulonglong2*)&be2[c0 + 4];
        #pragma unroll
        for (int i = 0; i < 8; i++) {
            acc[i][0] = b0.x; acc[i][1] = b0.y; acc[i][2] = b1.x; acc[i][3] = b1.y;
        }
    }
    __syncthreads();

    // -------- layer 2: K = 128 from Hs --------
    for (int chunk = 0; chunk < 8; ++chunk) {
        const int koff = chunk * BK;
        #pragma unroll
        for (int t = 0; t < 4; ++t) {
            int q = tid + t * NTHREADS;
            int row = q >> 5, col4 = (q & 31) * 4;
            *(float4*)&Ws[row * H_FEAT + col4] =
                *(const float4*)&We2[(size_t)(koff + row) * H_FEAT + col4];
        }
        __syncthreads();
        #pragma unroll
        for (int kk = 0; kk < BK; ++kk) {
            ulonglong2 w0 = *(const ulonglong2*)&Ws[kk * H_FEAT + c0];
            ulonglong2 w1 = *(const ulonglong2*)&Ws[kk * H_FEAT + c0 + 4];
            #pragma unroll
            for (int i = 0; i < 8; i++) {
                float a = Hs[(r0 + i) * HS_STRIDE + koff + kk];
                unsigned long long aa = pack2(a, a);
                fma2(acc[i][0], aa, w0.x);
                fma2(acc[i][1], aa, w0.y);
                fma2(acc[i][2], aa, w1.x);
                fma2(acc[i][3], aa, w1.y);
            }
        }
        __syncthreads();
    }

    // -------- epilogue: residual write + scatter-add --------
    #pragma unroll
    for (int i = 0; i < 8; i++) {
        const int e = e0 + r0 + i;
        float u[8];
        unpack2(acc[i][0], u[0], u[1]);
        unpack2(acc[i][1], u[2], u[3]);
        unpack2(acc[i][2], u[4], u[5]);
        unpack2(acc[i][3], u[6], u[7]);

        float* aggp = &agg[(size_t)rIdx[r0 + i] * D_FEAT + c0];
        red_add4(aggp,     u[0], u[1], u[2], u[3]);
        red_add4(aggp + 4, u[4], u[5], u[6], u[7]);

        const float4 efa = *(const float4*)&ef[(size_t)e * D_FEAT + c0];
        const float4 efb = *(const float4*)&ef[(size_t)e * D_FEAT + c0 + 4];
        float4 o0 = make_float4(u[0] + efa.x, u[1] + efa.y, u[2] + efa.z, u[3] + efa.w);
        float4 o1 = make_float4(u[4] + efb.x, u[5] + efb.y, u[6] + efb.z, u[7] + efb.w);
        *(float4*)&out_edges[(size_t)e * D_FEAT + c0]     = o0;
        *(float4*)&out_edges[(size_t)e * D_FEAT + c0 + 4] = o1;
    }
}

// ============================================================================
// Node kernel: n_upd = relu([nf, agg] @ Wn1 + bn1) @ Wn2 + bn2
//   out_nodes = nf + n_upd
// ============================================================================
__global__ void __launch_bounds__(NTHREADS, 3)
node_kernel(const float* __restrict__ nf, const float* __restrict__ agg,
            const float* __restrict__ Wn1, const float* __restrict__ bn1,
            const float* __restrict__ Wn2, const float* __restrict__ bn2,
            float* __restrict__ out_nodes)
{
    __shared__ __align__(16) float Xs[TM * XS_STRIDE];
    __shared__ __align__(16) float Ws[BK * H_FEAT];
    __shared__ __align__(16) float Hs[TM * HS_STRIDE];

    const int tid = threadIdx.x;
    const int ty = tid >> 4, tx = tid & 15;
    const int r0 = ty * 8, c0 = tx * 8;
    const int n0 = blockIdx.x * TM;

    unsigned long long acc[8][4];
    {
        ulonglong2 b0 = *(const ulonglong2*)&bn1[c0];
        ulonglong2 b1 = *(const ulonglong2*)&bn1[c0 + 4];
        #pragma unroll
        for (int i = 0; i < 8; i++) {
            acc[i][0] = b0.x; acc[i][1] = b0.y; acc[i][2] = b1.x; acc[i][3] = b1.y;
        }
    }

    // -------- layer 1: K = 256 over [nf | agg], chunks of 16 --------
    for (int chunk = 0; chunk < 16; ++chunk) {
        const int src  = chunk >> 3;   // 0: nf, 1: agg
        const int koff = (chunk & 7) * BK;
        {
            #pragma unroll
            for (int t = 0; t < 2; ++t) {
                int q = tid + t * NTHREADS;
                int row = q >> 2, j4 = (q & 3) * 4;
                int m = n0 + row;
                if (m >= N_NODES) m = N_NODES - 1;   // clamp (writes guarded later)
                const float* base = src ? agg : nf;
                float4 v = *(const float4*)&base[(size_t)m * D_FEAT + koff + j4];
                *(float4*)&Xs[row * XS_STRIDE + j4] = v;
            }
        }
        {
            const float* wbase = Wn1 + (size_t)(src * D_FEAT + koff) * H_FEAT;
            #pragma unroll
            for (int t = 0; t < 4; ++t) {
                int q = tid + t * NTHREADS;
                int row = q >> 5, col4 = (q & 31) * 4;
                *(float4*)&Ws[row * H_FEAT + col4] =
                    *(const float4*)&wbase[(size_t)row * H_FEAT + col4];
            }
        }
        __syncthreads();
        #pragma unroll
        for (int kk = 0; kk < BK; ++kk) {
            ulonglong2 w0 = *(const ulonglong2*)&Ws[kk * H_FEAT + c0];
            ulonglong2 w1 = *(const ulonglong2*)&Ws[kk * H_FEAT + c0 + 4];
            #pragma unroll
            for (int i = 0; i < 8; i++) {
                float a = Xs[(r0 + i) * XS_STRIDE + kk];
                unsigned long long aa = pack2(a, a);
                fma2(acc[i][0], aa, w0.x);
                fma2(acc[i][1], aa, w0.y);
                fma2(acc[i][2], aa, w1.x);
                fma2(acc[i][3], aa, w1.y);
            }
        }
        __syncthreads();
    }

    // -------- ReLU -> Hs --------
    #pragma unroll
    for (int i = 0; i < 8; i++) {
        float h[8];
        unpack2(acc[i][0], h[0], h[1]);
        unpack2(acc[i][1], h[2], h[3]);
        unpack2(acc[i][2], h[4], h[5]);
        unpack2(acc[i][3], h[6], h[7]);
        #pragma unroll
        for (int j = 0; j < 8; j++) h[j] = fmaxf(h[j], 0.0f);
        float* hp = &Hs[(r0 + i) * HS_STRIDE + c0];
        *(float4*)hp       = make_float4(h[0], h[1], h[2], h[3]);
        *(float4*)(hp + 4) = make_float4(h[4], h[5], h[6], h[7]);
    }
    {
        ulonglong2 b0 = *(const ulonglong2*)&bn2[c0];
        ulonglong2 b1 = *(const ulonglong2*)&bn2[c0 + 4];
        #pragma unroll
        for (int i = 0; i < 8; i++) {
            acc[i][0] = b0.x; acc[i][1] = b0.y; acc[i][2] = b1.x; acc[i][3] = b1.y;
        }
    }
    __syncthreads();

    // -------- layer 2: K = 128 from Hs --------
    for (int chunk = 0; chunk < 8; ++chunk) {
        const int koff = chunk * BK;
        #pragma unroll
        for (int t = 0; t < 4; ++t) {
            int q = tid + t * NTHREADS;
            int row = q >> 5, col4 = (q & 31) * 4;
            *(float4*)&Ws[row * H_FEAT + col4] =
                *(const float4*)&Wn2[(size_t)(koff + row) * H_FEAT + col4];
        }
        __syncthreads();
        #pragma unroll
        for (int kk = 0; kk < BK; ++kk) {
            ulonglong2 w0 = *(const ulonglong2*)&Ws[kk * H_FEAT + c0];
            ulonglong2 w1 = *(const ulonglong2*)&Ws[kk * H_FEAT + c0 + 4];
            #pragma unroll
            for (int i = 0; i < 8; i++) {
                float a = Hs[(r0 + i) * HS_STRIDE + koff + kk];
                unsigned long long aa = pack2(a, a);
                fma2(acc[i][0], aa, w0.x);
                fma2(acc[i][1], aa, w0.y);
                fma2(acc[i][2], aa, w1.x);
                fma2(acc[i][3], aa, w1.y);
            }
        }
        __syncthreads();
    }

    // -------- epilogue: residual write (guarded) --------
    #pragma unroll
    for (int i = 0; i < 8; i++) {
        const int m = n0 + r0 + i;
        if (m < N_NODES) {
            float u[8];
            unpack2(acc[i][0], u[0], u[1]);
            unpack2(acc[i][1], u[2], u[3]);
            unpack2(acc[i][2], u[4], u[5]);
            unpack2(acc[i][3], u[6], u[7]);
            const float4 na = *(const float4*)&nf[(size_t)m * D_FEAT + c0];
            const float4 nb = *(const float4*)&nf[(size_t)m * D_FEAT + c0 + 4];
            float4 o0 = make_float4(u[0] + na.x, u[1] + na.y, u[2] + na.z, u[3] + na.w);
            float4 o1 = make_float4(u[4] + nb.x, u[5] + nb.y, u[6] + nb.z, u[7] + nb.w);
            *(float4*)&out_nodes[(size_t)m * D_FEAT + c0]     = o0;
            *(float4*)&out_nodes[(size_t)m * D_FEAT + c0 + 4] = o1;
        }
    }
}

// ============================================================================
extern "C" void kernel_launch(void* const* d_in, const int* in_sizes, int n_in,
                              void* d_out, int out_size)
{
    const float* nf  = (const float*)d_in[0];
    const float* ef  = (const float*)d_in[1];
    const int*   snd = (const int*)  d_in[2];
    const int*   rcv = (const int*)  d_in[3];
    const float* We1 = (const float*)d_in[4];
    const float* be1 = (const float*)d_in[5];
    const float* We2 = (const float*)d_in[6];
    const float* be2 = (const float*)d_in[7];
    const float* Wn1 = (const float*)d_in[8];
    const float* bn1 = (const float*)d_in[9];
    const float* Wn2 = (const float*)d_in[10];
    const float* bn2 = (const float*)d_in[11];

    float* out_nodes = (float*)d_out;                            // [N, D] first
    float* out_edges = (float*)d_out + (size_t)N_NODES * D_FEAT; // [E, D] second

    float* aggp = nullptr;
    cudaGetSymbolAddress((void**)&aggp, g_agg);
    cudaMemsetAsync(aggp, 0, (size_t)N_NODES * D_FEAT * sizeof(float));

    edge_kernel<<<N_EDGES / TM, NTHREADS>>>(nf, ef, snd, rcv,
                                            We1, be1, We2, be2,
                                            out_edges, aggp);
    node_kernel<<<(N_NODES + TM - 1) / TM, NTHREADS>>>(nf, aggp,
                                                       Wn1, bn1, Wn2, bn2,
                                                       out_nodes);
}

// round 9
// speedup vs baseline: 1.4717x; 1.0005x over previous
#include <cuda_runtime.h>
#include <cstdint>

#define D_FEAT   128
#define H_FEAT   128
#define N_NODES  100000
#define N_EDGES  800000

#define TM       64      // rows (edges/nodes) per CTA
#define BK       16      // K-chunk
#define NTHREADS 128     // 16 (tx) x 8 (ty); thread tile = 8 rows x 8 cols
#define XS_STRIDE (BK + 4)      // 20
#define HS_STRIDE (D_FEAT + 4)  // 132

// scatter-sum scratch (51.2 MB). __device__ global: allowed (no alloc).
__device__ float g_agg[(size_t)N_NODES * D_FEAT];

// ---- packed f32x2 helpers (Blackwell FFMA2 path, PTX-only) ----
__device__ __forceinline__ void fma2(unsigned long long &c,
                                     unsigned long long a,
                                     unsigned long long b) {
    asm("fma.rn.f32x2 %0, %1, %2, %3;" : "=l"(c) : "l"(a), "l"(b), "l"(c));
}
__device__ __forceinline__ unsigned long long pack2(float lo, float hi) {
    unsigned long long r;
    asm("mov.b64 %0, {%1, %2};" : "=l"(r) : "f"(lo), "f"(hi));
    return r;
}
__device__ __forceinline__ void unpack2(unsigned long long v, float &lo, float &hi) {
    asm("mov.b64 {%0, %1}, %2;" : "=f"(lo), "=f"(hi) : "l"(v));
}
__device__ __forceinline__ void red_add4(float* p, float a, float b, float c, float d) {
    asm volatile("red.global.add.v4.f32 [%0], {%1, %2, %3, %4};"
                 :: "l"(p), "f"(a), "f"(b), "f"(c), "f"(d) : "memory");
}

// ============================================================================
// Edge kernel: e_upd = relu([nf[s], nf[r], ef] @ We1 + be1) @ We2 + be2
//   out_edges = ef + e_upd ;  red-add e_upd into g_agg[receiver]
// ============================================================================
__global__ void __launch_bounds__(NTHREADS, 3)
edge_kernel(const float* __restrict__ nf, const float* __restrict__ ef,
            const int* __restrict__ snd, const int* __restrict__ rcv,
            const float* __restrict__ We1, const float* __restrict__ be1,
            const float* __restrict__ We2, const float* __restrict__ be2,
            float* __restrict__ out_edges, float* __restrict__ agg)
{
    __shared__ __align__(16) int   sIdx[TM];
    __shared__ __align__(16) int   rIdx[TM];
    __shared__ __align__(16) float Xs[TM * XS_STRIDE];
    __shared__ __align__(16) float Ws[BK * H_FEAT];
    __shared__ __align__(16) float Hs[TM * HS_STRIDE];

    const int tid = threadIdx.x;
    const int ty = tid >> 4, tx = tid & 15;
    const int r0 = ty * 8, c0 = tx * 8;
    const int e0 = blockIdx.x * TM;

    if (tid < TM) { sIdx[tid] = snd[e0 + tid]; rIdx[tid] = rcv[e0 + tid]; }

    unsigned long long acc[8][4];
    {   // init with layer-1 bias
        ulonglong2 b0 = *(const ulonglong2*)&be1[c0];
        ulonglong2 b1 = *(const ulonglong2*)&be1[c0 + 4];
        #pragma unroll
        for (int i = 0; i < 8; i++) {
            acc[i][0] = b0.x; acc[i][1] = b0.y; acc[i][2] = b1.x; acc[i][3] = b1.y;
        }
    }
    __syncthreads();

    // -------- layer 1: K = 384 over 3 gathered sources, chunks of 16 --------
    for (int chunk = 0; chunk < 24; ++chunk) {
        const int src  = chunk >> 3;          // 0: sender nf, 1: receiver nf, 2: ef
        const int koff = (chunk & 7) * BK;
        {   // Xs tile: 64 rows x 16 floats = 256 float4, 2 per thread
            #pragma unroll
            for (int t = 0; t < 2; ++t) {
                int q = tid + t * NTHREADS;
                int row = q >> 2, j4 = (q & 3) * 4;
                size_t grow;
                const float* base;
                if (src == 0)      { grow = (size_t)sIdx[row]; base = nf; }
                else if (src == 1) { grow = (size_t)rIdx[row]; base = nf; }
                else               { grow = (size_t)(e0 + row); base = ef; }
                float4 v = *(const float4*)&base[grow * D_FEAT + koff + j4];
                *(float4*)&Xs[row * XS_STRIDE + j4] = v;
            }
        }
        {   // Ws tile: 16 x 128 = 512 float4, 4 per thread
            const float* wbase = We1 + (size_t)(src * D_FEAT + koff) * H_FEAT;
            #pragma unroll
            for (int t = 0; t < 4; ++t) {
                int q = tid + t * NTHREADS;
                int row = q >> 5, col4 = (q & 31) * 4;
                *(float4*)&Ws[row * H_FEAT + col4] =
                    *(const float4*)&wbase[(size_t)row * H_FEAT + col4];
            }
        }
        __syncthreads();
        #pragma unroll
        for (int kk = 0; kk < BK; ++kk) {
            ulonglong2 w0 = *(const ulonglong2*)&Ws[kk * H_FEAT + c0];
            ulonglong2 w1 = *(const ulonglong2*)&Ws[kk * H_FEAT + c0 + 4];
            #pragma unroll
            for (int i = 0; i < 8; i++) {
                float a = Xs[(r0 + i) * XS_STRIDE + kk];
                unsigned long long aa = pack2(a, a);
                fma2(acc[i][0], aa, w0.x);
                fma2(acc[i][1], aa, w0.y);
                fma2(acc[i][2], aa, w1.x);
                fma2(acc[i][3], aa, w1.y);
            }
        }
        __syncthreads();
    }

    // -------- ReLU -> Hs --------
    #pragma unroll
    for (int i = 0; i < 8; i++) {
        float h[8];
        unpack2(acc[i][0], h[0], h[1]);
        unpack2(acc[i][1], h[2], h[3]);
        unpack2(acc[i][2], h[4], h[5]);
        unpack2(acc[i][3], h[6], h[7]);
        #pragma unroll
        for (int j = 0; j < 8; j++) h[j] = fmaxf(h[j], 0.0f);
        float* hp = &Hs[(r0 + i) * HS_STRIDE + c0];
        *(float4*)hp       = make_float4(h[0], h[1], h[2], h[3]);
        *(float4*)(hp + 4) = make_float4(h[4], h[5], h[6], h[7]);
    }
    {   // init with layer-2 bias
        ulonglong2 b0 = *(const ulonglong2*)&be2[c0];
        ulonglong2 b1 = *(const ulonglong2*)&be2[c0 + 4];
        #pragma unroll
        for (int i = 0; i < 8; i++) {
            acc[i][0] = b0.x; acc[i][1] = b0.y; acc[i][2] = b1.x; acc[i][3] = b1.y;
        }
    }
    __syncthreads();

    // -------- layer 2: K = 128 from Hs --------
    for (int chunk = 0; chunk < 8; ++chunk) {
        const int koff = chunk * BK;
        #pragma unroll
        for (int t = 0; t < 4; ++t) {
            int q = tid + t * NTHREADS;
            int row = q >> 5, col4 = (q & 31) * 4;
            *(float4*)&Ws[row * H_FEAT + col4] =
                *(const float4*)&We2[(size_t)(koff + row) * H_FEAT + col4];
        }
        __syncthreads();
        #pragma unroll
        for (int kk = 0; kk < BK; ++kk) {
            ulonglong2 w0 = *(const ulonglong2*)&Ws[kk * H_FEAT + c0];
            ulonglong2 w1 = *(const ulonglong2*)&Ws[kk * H_FEAT + c0 + 4];
            #pragma unroll
            for (int i = 0; i < 8; i++) {
                float a = Hs[(r0 + i) * HS_STRIDE + koff + kk];
                unsigned long long aa = pack2(a, a);
                fma2(acc[i][0], aa, w0.x);
                fma2(acc[i][1], aa, w0.y);
                fma2(acc[i][2], aa, w1.x);
                fma2(acc[i][3], aa, w1.y);
            }
        }
        __syncthreads();
    }

    // -------- epilogue: residual write + scatter-add --------
    #pragma unroll
    for (int i = 0; i < 8; i++) {
        const int e = e0 + r0 + i;
        float u[8];
        unpack2(acc[i][0], u[0], u[1]);
        unpack2(acc[i][1], u[2], u[3]);
        unpack2(acc[i][2], u[4], u[5]);
        unpack2(acc[i][3], u[6], u[7]);

        float* aggp = &agg[(size_t)rIdx[r0 + i] * D_FEAT + c0];
        red_add4(aggp,     u[0], u[1], u[2], u[3]);
        red_add4(aggp + 4, u[4], u[5], u[6], u[7]);

        const float4 efa = *(const float4*)&ef[(size_t)e * D_FEAT + c0];
        const float4 efb = *(const float4*)&ef[(size_t)e * D_FEAT + c0 + 4];
        float4 o0 = make_float4(u[0] + efa.x, u[1] + efa.y, u[2] + efa.z, u[3] + efa.w);
        float4 o1 = make_float4(u[4] + efb.x, u[5] + efb.y, u[6] + efb.z, u[7] + efb.w);
        *(float4*)&out_edges[(size_t)e * D_FEAT + c0]     = o0;
        *(float4*)&out_edges[(size_t)e * D_FEAT + c0 + 4] = o1;
    }
}

// ============================================================================
// Node kernel: n_upd = relu([nf, agg] @ Wn1 + bn1) @ Wn2 + bn2
//   out_nodes = nf + n_upd
// ============================================================================
__global__ void __launch_bounds__(NTHREADS, 3)
node_kernel(const float* __restrict__ nf, const float* __restrict__ agg,
            const float* __restrict__ Wn1, const float* __restrict__ bn1,
            const float* __restrict__ Wn2, const float* __restrict__ bn2,
            float* __restrict__ out_nodes)
{
    __shared__ __align__(16) float Xs[TM * XS_STRIDE];
    __shared__ __align__(16) float Ws[BK * H_FEAT];
    __shared__ __align__(16) float Hs[TM * HS_STRIDE];

    const int tid = threadIdx.x;
    const int ty = tid >> 4, tx = tid & 15;
    const int r0 = ty * 8, c0 = tx * 8;
    const int n0 = blockIdx.x * TM;

    unsigned long long acc[8][4];
    {
        ulonglong2 b0 = *(const ulonglong2*)&bn1[c0];
        ulonglong2 b1 = *(const ulonglong2*)&bn1[c0 + 4];
        #pragma unroll
        for (int i = 0; i < 8; i++) {
            acc[i][0] = b0.x; acc[i][1] = b0.y; acc[i][2] = b1.x; acc[i][3] = b1.y;
        }
    }

    // -------- layer 1: K = 256 over [nf | agg], chunks of 16 --------
    for (int chunk = 0; chunk < 16; ++chunk) {
        const int src  = chunk >> 3;   // 0: nf, 1: agg
        const int koff = (chunk & 7) * BK;
        {
            #pragma unroll
            for (int t = 0; t < 2; ++t) {
                int q = tid + t * NTHREADS;
                int row = q >> 2, j4 = (q & 3) * 4;
                int m = n0 + row;
                if (m >= N_NODES) m = N_NODES - 1;   // clamp (writes guarded later)
                const float* base = src ? agg : nf;
                float4 v = *(const float4*)&base[(size_t)m * D_FEAT + koff + j4];
                *(float4*)&Xs[row * XS_STRIDE + j4] = v;
            }
        }
        {
            const float* wbase = Wn1 + (size_t)(src * D_FEAT + koff) * H_FEAT;
            #pragma unroll
            for (int t = 0; t < 4; ++t) {
                int q = tid + t * NTHREADS;
                int row = q >> 5, col4 = (q & 31) * 4;
                *(float4*)&Ws[row * H_FEAT + col4] =
                    *(const float4*)&wbase[(size_t)row * H_FEAT + col4];
            }
        }
        __syncthreads();
        #pragma unroll
        for (int kk = 0; kk < BK; ++kk) {
            ulonglong2 w0 = *(const ulonglong2*)&Ws[kk * H_FEAT + c0];
            ulonglong2 w1 = *(const ulonglong2*)&Ws[kk * H_FEAT + c0 + 4];
            #pragma unroll
            for (int i = 0; i < 8; i++) {
                float a = Xs[(r0 + i) * XS_STRIDE + kk];
                unsigned long long aa = pack2(a, a);
                fma2(acc[i][0], aa, w0.x);
                fma2(acc[i][1], aa, w0.y);
                fma2(acc[i][2], aa, w1.x);
                fma2(acc[i][3], aa, w1.y);
            }
        }
        __syncthreads();
    }

    // -------- ReLU -> Hs --------
    #pragma unroll
    for (int i = 0; i < 8; i++) {
        float h[8];
        unpack2(acc[i][0], h[0], h[1]);
        unpack2(acc[i][1], h[2], h[3]);
        unpack2(acc[i][2], h[4], h[5]);
        unpack2(acc[i][3], h[6], h[7]);
        #pragma unroll
        for (int j = 0; j < 8; j++) h[j] = fmaxf(h[j], 0.0f);
        float* hp = &Hs[(r0 + i) * HS_STRIDE + c0];
        *(float4*)hp       = make_float4(h[0], h[1], h[2], h[3]);
        *(float4*)(hp + 4) = make_float4(h[4], h[5], h[6], h[7]);
    }
    {
        ulonglong2 b0 = *(const ulonglong2*)&bn2[c0];
        ulonglong2 b1 = *(const ulonglong2*)&bn2[c0 + 4];
        #pragma unroll
        for (int i = 0; i < 8; i++) {
            acc[i][0] = b0.x; acc[i][1] = b0.y; acc[i][2] = b1.x; acc[i][3] = b1.y;
        }
    }
    __syncthreads();

    // -------- layer 2: K = 128 from Hs --------
    for (int chunk = 0; chunk < 8; ++chunk) {
        const int koff = chunk * BK;
        #pragma unroll
        for (int t = 0; t < 4; ++t) {
            int q = tid + t * NTHREADS;
            int row = q >> 5, col4 = (q & 31) * 4;
            *(float4*)&Ws[row * H_FEAT + col4] =
                *(const float4*)&Wn2[(size_t)(koff + row) * H_FEAT + col4];
        }
        __syncthreads();
        #pragma unroll
        for (int kk = 0; kk < BK; ++kk) {
            ulonglong2 w0 = *(const ulonglong2*)&Ws[kk * H_FEAT + c0];
            ulonglong2 w1 = *(const ulonglong2*)&Ws[kk * H_FEAT + c0 + 4];
            #pragma unroll
            for (int i = 0; i < 8; i++) {
                float a = Hs[(r0 + i) * HS_STRIDE + koff + kk];
                unsigned long long aa = pack2(a, a);
                fma2(acc[i][0], aa, w0.x);
                fma2(acc[i][1], aa, w0.y);
                fma2(acc[i][2], aa, w1.x);
                fma2(acc[i][3], aa, w1.y);
            }
        }
        __syncthreads();
    }

    // -------- epilogue: residual write (guarded) --------
    #pragma unroll
    for (int i = 0; i < 8; i++) {
        const int m = n0 + r0 + i;
        if (m < N_NODES) {
            float u[8];
            unpack2(acc[i][0], u[0], u[1]);
            unpack2(acc[i][1], u[2], u[3]);
            unpack2(acc[i][2], u[4], u[5]);
            unpack2(acc[i][3], u[6], u[7]);
            const float4 na = *(const float4*)&nf[(size_t)m * D_FEAT + c0];
            const float4 nb = *(const float4*)&nf[(size_t)m * D_FEAT + c0 + 4];
            float4 o0 = make_float4(u[0] + na.x, u[1] + na.y, u[2] + na.z, u[3] + na.w);
            float4 o1 = make_float4(u[4] + nb.x, u[5] + nb.y, u[6] + nb.z, u[7] + nb.w);
            *(float4*)&out_nodes[(size_t)m * D_FEAT + c0]     = o0;
            *(float4*)&out_nodes[(size_t)m * D_FEAT + c0 + 4] = o1;
        }
    }
}

// ============================================================================
extern "C" void kernel_launch(void* const* d_in, const int* in_sizes, int n_in,
                              void* d_out, int out_size)
{
    const float* nf  = (const float*)d_in[0];
    const float* ef  = (const float*)d_in[1];
    const int*   snd = (const int*)  d_in[2];
    const int*   rcv = (const int*)  d_in[3];
    const float* We1 = (const float*)d_in[4];
    const float* be1 = (const float*)d_in[5];
    const float* We2 = (const float*)d_in[6];
    const float* be2 = (const float*)d_in[7];
    const float* Wn1 = (const float*)d_in[8];
    const float* bn1 = (const float*)d_in[9];
    const float* Wn2 = (const float*)d_in[10];
    const float* bn2 = (const float*)d_in[11];

    float* out_nodes = (float*)d_out;                            // [N, D] first
    float* out_edges = (float*)d_out + (size_t)N_NODES * D_FEAT; // [E, D] second

    float* aggp = nullptr;
    cudaGetSymbolAddress((void**)&aggp, g_agg);
    cudaMemsetAsync(aggp, 0, (size_t)N_NODES * D_FEAT * sizeof(float));

    edge_kernel<<<N_EDGES / TM, NTHREADS>>>(nf, ef, snd, rcv,
                                            We1, be1, We2, be2,
                                            out_edges, aggp);
    node_kernel<<<(N_NODES + TM - 1) / TM, NTHREADS>>>(nf, aggp,
                                                       Wn1, bn1, Wn2, bn2,
                                                       out_nodes);
}